// round 11
// baseline (speedup 1.0000x reference)
#include <cuda_runtime.h>
#include <cuda_bf16.h>
#include <cstdint>
#include <math.h>

// Problem constants
#define S_LEN  2048
#define DMODEL 4096
#define HQ     32
#define HKV    8
#define HD     128
#define DKV    (HKV * HD)   // 1024

// ---------------------------------------------------------------------------
// Scratch (device globals)
// ---------------------------------------------------------------------------
__device__ float g_v[(size_t)S_LEN * DKV];
__device__ float g_cost[(size_t)S_LEN * 64];
__device__ float g_sint[(size_t)S_LEN * 64];

__device__ __nv_bfloat16 g_xh[(size_t)S_LEN * DMODEL],  g_xl[(size_t)S_LEN * DMODEL];
__device__ __nv_bfloat16 g_wqh[(size_t)DMODEL * DMODEL], g_wql[(size_t)DMODEL * DMODEL];
__device__ __nv_bfloat16 g_wkh[(size_t)DKV * DMODEL],    g_wkl[(size_t)DKV * DMODEL];
__device__ __nv_bfloat16 g_wvh[(size_t)DKV * DMODEL],    g_wvl[(size_t)DKV * DMODEL];
__device__ __nv_bfloat16 g_woh[(size_t)DMODEL * DMODEL], g_wol[(size_t)DMODEL * DMODEL];
__device__ __nv_bfloat16 g_qh[(size_t)S_LEN * DMODEL],   g_ql[(size_t)S_LEN * DMODEL];
__device__ __nv_bfloat16 g_kh[(size_t)S_LEN * DKV],      g_kl[(size_t)S_LEN * DKV];
__device__ __nv_bfloat16 g_vth[(size_t)DKV * S_LEN],     g_vtl[(size_t)DKV * S_LEN];
__device__ __nv_bfloat16 g_ah[(size_t)S_LEN * DMODEL],   g_al[(size_t)S_LEN * DMODEL];

// ---------------------------------------------------------------------------
// PTX helpers
// ---------------------------------------------------------------------------
__device__ __forceinline__ uint32_t smem_u32(const void* p) {
    uint32_t a;
    asm("{ .reg .u64 t; cvta.to.shared.u64 t, %1; cvt.u32.u64 %0, t; }"
        : "=r"(a) : "l"(p));
    return a;
}
__device__ __forceinline__ void ldsm_x4(uint32_t r[4], uint32_t addr) {
    asm volatile("ldmatrix.sync.aligned.m8n8.x4.shared.b16 {%0,%1,%2,%3}, [%4];"
        : "=r"(r[0]), "=r"(r[1]), "=r"(r[2]), "=r"(r[3]) : "r"(addr));
}
__device__ __forceinline__ void mma_bf16(float d[4], const uint32_t a[4],
                                         const uint32_t b[2]) {
    asm volatile(
        "mma.sync.aligned.m16n8k16.row.col.f32.bf16.bf16.f32 "
        "{%0,%1,%2,%3}, {%4,%5,%6,%7}, {%8,%9}, {%0,%1,%2,%3};"
        : "+f"(d[0]), "+f"(d[1]), "+f"(d[2]), "+f"(d[3])
        : "r"(a[0]), "r"(a[1]), "r"(a[2]), "r"(a[3]), "r"(b[0]), "r"(b[1]));
}
#define CP_ASYNC16(sm_addr, gptr) \
    asm volatile("cp.async.cg.shared.global [%0], [%1], 16;" \
                 :: "r"(sm_addr), "l"(gptr) : "memory")
#define CP_COMMIT() asm volatile("cp.async.commit_group;" ::: "memory")
#define CP_WAIT0()  asm volatile("cp.async.wait_group 0;" ::: "memory")

__device__ __forceinline__ void split2(float x, __nv_bfloat16& h, __nv_bfloat16& l) {
    h = __float2bfloat16(x);
    l = __float2bfloat16(x - __bfloat162float(h));
}
__device__ __forceinline__ uint32_t packpair(__nv_bfloat16 a, __nv_bfloat16 b) {
    __nv_bfloat162 t = __halves2bfloat162(a, b);
    return *reinterpret_cast<uint32_t*>(&t);
}

// ---------------------------------------------------------------------------
// GEMM mainloop: acc = (Ah+Al)[128 rows@row0] x (Bh+Bl)[128 rows@col0]^T
// ---------------------------------------------------------------------------
#define TILE_B (128 * 80)
#define STAGE_B (4 * TILE_B)
#define GSMEM  (2 * STAGE_B)

__device__ __forceinline__ void gemm_main(
    const __nv_bfloat16* __restrict__ Ah, const __nv_bfloat16* __restrict__ Al,
    const __nv_bfloat16* __restrict__ Bh, const __nv_bfloat16* __restrict__ Bl,
    int K, int lda, int ldb, int row0, int col0, char* smem,
    float acc[4][4][4])
{
    const uint32_t sbase = smem_u32(smem);
    const int tid  = threadIdx.x;
    const int lane = tid & 31;
    const int w    = tid >> 5;
    const int wm   = (w & 1) * 64;
    const int wn   = (w >> 1) * 32;

    const int pr  = (tid << 1) >> 2;
    const int pr1 = ((tid << 1) + 1) >> 2;
    const int pc  = ((tid << 1) & 3) * 8;
    const int pc1 = (((tid << 1) + 1) & 3) * 8;

#pragma unroll
    for (int i = 0; i < 4; i++)
#pragma unroll
        for (int j = 0; j < 4; j++)
#pragma unroll
            for (int e = 0; e < 4; e++) acc[i][j][e] = 0.f;

    const int KT = K / 32;

#define PREFETCH(kt, stage) do {                                               \
    const int k0 = (kt) * 32;                                                  \
    const uint32_t ss = sbase + (stage) * STAGE_B;                             \
    uint32_t o0 = (uint32_t)(pr  * 80 + pc  * 2);                              \
    uint32_t o1 = (uint32_t)(pr1 * 80 + pc1 * 2);                              \
    CP_ASYNC16(ss + o0,              Ah + (long long)(row0 + pr ) * lda + k0 + pc ); \
    CP_ASYNC16(ss + o1,              Ah + (long long)(row0 + pr1) * lda + k0 + pc1); \
    CP_ASYNC16(ss + TILE_B + o0,     Al + (long long)(row0 + pr ) * lda + k0 + pc ); \
    CP_ASYNC16(ss + TILE_B + o1,     Al + (long long)(row0 + pr1) * lda + k0 + pc1); \
    CP_ASYNC16(ss + 2 * TILE_B + o0, Bh + (long long)(col0 + pr ) * ldb + k0 + pc ); \
    CP_ASYNC16(ss + 2 * TILE_B + o1, Bh + (long long)(col0 + pr1) * ldb + k0 + pc1); \
    CP_ASYNC16(ss + 3 * TILE_B + o0, Bl + (long long)(col0 + pr ) * ldb + k0 + pc ); \
    CP_ASYNC16(ss + 3 * TILE_B + o1, Bl + (long long)(col0 + pr1) * ldb + k0 + pc1); \
} while (0)

    PREFETCH(0, 0);
    CP_COMMIT();

    for (int kt = 0; kt < KT; kt++) {
        CP_WAIT0();
        __syncthreads();
        if (kt + 1 < KT) {
            PREFETCH(kt + 1, (kt + 1) & 1);
            CP_COMMIT();
        }
        const uint32_t ss = sbase + (kt & 1) * STAGE_B;
        const uint32_t ah0 = ss, al0 = ss + TILE_B;
        const uint32_t bh0 = ss + 2 * TILE_B, bl0 = ss + 3 * TILE_B;

#pragma unroll
        for (int kc = 0; kc < 2; kc++) {
            const int kb = kc * 16;
            uint32_t afh[4][4], afl[4][4];
            {
                int rr = lane & 15;
                int cc = kb + ((lane >> 4) << 3);
#pragma unroll
                for (int mi = 0; mi < 4; mi++) {
                    uint32_t off = (uint32_t)((wm + mi * 16 + rr) * 80 + cc * 2);
                    ldsm_x4(afh[mi], ah0 + off);
                    ldsm_x4(afl[mi], al0 + off);
                }
            }
            {
                int rr    = lane & 7;
                int cc    = kb + (((lane >> 3) & 1) << 3);
                int njoff = (lane >> 4) << 3;
#pragma unroll
                for (int njp = 0; njp < 2; njp++) {
                    uint32_t bh4[4], bl4[4];
                    uint32_t off = (uint32_t)((wn + njp * 16 + njoff + rr) * 80 + cc * 2);
                    ldsm_x4(bh4, bh0 + off);
                    ldsm_x4(bl4, bl0 + off);
#pragma unroll
                    for (int mi = 0; mi < 4; mi++) {
                        mma_bf16(acc[mi][2 * njp], afh[mi], bh4);
                        mma_bf16(acc[mi][2 * njp], afh[mi], bl4);
                        mma_bf16(acc[mi][2 * njp], afl[mi], bh4);
                        mma_bf16(acc[mi][2 * njp + 1], afh[mi], bh4 + 2);
                        mma_bf16(acc[mi][2 * njp + 1], afh[mi], bl4 + 2);
                        mma_bf16(acc[mi][2 * njp + 1], afl[mi], bh4 + 2);
                    }
                }
            }
        }
        __syncthreads();
    }
#undef PREFETCH
}

// Rope + scale + split epilogue (Q/K projections)
__device__ __forceinline__ void epilogue_rope(
    float acc[4][4][4], int row0, int col0,
    __nv_bfloat16* dh, __nv_bfloat16* dl, int ld, float ps)
{
    const int lane = threadIdx.x & 31;
    const int w    = threadIdx.x >> 5;
    const int wm   = (w & 1) * 64;
    const int wn   = (w >> 1) * 32;
#pragma unroll
    for (int mi = 0; mi < 4; mi++)
#pragma unroll
        for (int nj = 0; nj < 4; nj++) {
            int r0 = row0 + wm + mi * 16 + (lane >> 2);
            int r1 = r0 + 8;
            int c  = col0 + wn + nj * 8 + (lane & 3) * 2;
            int i  = (c & 127) >> 1;
            float c0 = g_cost[r0 * 64 + i], s0 = g_sint[r0 * 64 + i];
            float c1 = g_cost[r1 * 64 + i], s1 = g_sint[r1 * 64 + i];
            float x1 = acc[mi][nj][0], x2 = acc[mi][nj][1];
            float o1 = (x1 * c0 - x2 * s0) * ps;
            float o2 = (x1 * s0 + x2 * c0) * ps;
            __nv_bfloat16 hh0, hh1, ll0, ll1;
            split2(o1, hh0, ll0); split2(o2, hh1, ll1);
            *(uint32_t*)(dh + (size_t)r0 * ld + c) = packpair(hh0, hh1);
            *(uint32_t*)(dl + (size_t)r0 * ld + c) = packpair(ll0, ll1);
            x1 = acc[mi][nj][2]; x2 = acc[mi][nj][3];
            o1 = (x1 * c1 - x2 * s1) * ps;
            o2 = (x1 * s1 + x2 * c1) * ps;
            split2(o1, hh0, ll0); split2(o2, hh1, ll1);
            *(uint32_t*)(dh + (size_t)r1 * ld + c) = packpair(hh0, hh1);
            *(uint32_t*)(dl + (size_t)r1 * ld + c) = packpair(ll0, ll1);
        }
}

// fp32 store epilogue
__device__ __forceinline__ void epilogue_f32(
    float acc[4][4][4], int row0, int col0, float* C, int ldc)
{
    const int lane = threadIdx.x & 31;
    const int w    = threadIdx.x >> 5;
    const int wm   = (w & 1) * 64;
    const int wn   = (w >> 1) * 32;
#pragma unroll
    for (int mi = 0; mi < 4; mi++)
#pragma unroll
        for (int nj = 0; nj < 4; nj++) {
            int r = row0 + wm + mi * 16 + (lane >> 2);
            int c = col0 + wn + nj * 8 + (lane & 3) * 2;
            float* p0 = C + (long long)r * ldc + c;
            p0[0] = acc[mi][nj][0];
            p0[1] = acc[mi][nj][1];
            float* p1 = C + (long long)(r + 8) * ldc + c;
            p1[0] = acc[mi][nj][2];
            p1[1] = acc[mi][nj][3];
        }
}

// Merged Q/K/V projection with fused RoPE epilogues.
// grid (48, 16): x 0-31 -> Q (rope+scale), 32-39 -> K (rope), 40-47 -> V (fp32)
__global__ __launch_bounds__(256) void tcg_qkv() {
    extern __shared__ char smem[];
    const int cb   = blockIdx.x;
    const int row0 = blockIdx.y * 128;
    float acc[4][4][4];
    if (cb < 32) {
        gemm_main(g_xh, g_xl, g_wqh, g_wql, DMODEL, DMODEL, DMODEL,
                  row0, cb * 128, smem, acc);
        epilogue_rope(acc, row0, cb * 128, g_qh, g_ql, DMODEL,
                      0.08838834764831845f);
    } else if (cb < 40) {
        gemm_main(g_xh, g_xl, g_wkh, g_wkl, DMODEL, DMODEL, DMODEL,
                  row0, (cb - 32) * 128, smem, acc);
        epilogue_rope(acc, row0, (cb - 32) * 128, g_kh, g_kl, DKV, 1.0f);
    } else {
        gemm_main(g_xh, g_xl, g_wvh, g_wvl, DMODEL, DMODEL, DMODEL,
                  row0, (cb - 40) * 128, smem, acc);
        epilogue_f32(acc, row0, (cb - 40) * 128, g_v, DKV);
    }
}

// Generic NT GEMM (wo)
__global__ __launch_bounds__(256) void tcg_nt(
    const __nv_bfloat16* __restrict__ Ah, const __nv_bfloat16* __restrict__ Al,
    const __nv_bfloat16* __restrict__ Bh, const __nv_bfloat16* __restrict__ Bl,
    float* __restrict__ C, int K, int lda, int ldb, int ldc)
{
    extern __shared__ char smem[];
    float acc[4][4][4];
    gemm_main(Ah, Al, Bh, Bl, K, lda, ldb,
              blockIdx.y * 128, blockIdx.x * 128, smem, acc);
    epilogue_f32(acc, blockIdx.y * 128, blockIdx.x * 128, C, ldc);
}

// ---------------------------------------------------------------------------
// cos/sin tables (identical arithmetic to previous rope_split)
// ---------------------------------------------------------------------------
__global__ void init_tables() {
    int s = blockIdx.x;
    int i = threadIdx.x;   // 0..63
    float invf = (float)(1.0 / pow(10000.0, (double)i / 64.0));
    float ang = (float)s * invf;
    double sd, cd;
    sincos((double)ang, &sd, &cd);
    g_cost[s * 64 + i] = (float)cd;
    g_sint[s * 64 + i] = (float)sd;
}

// ---------------------------------------------------------------------------
// Fused flash attention (unchanged from R8)
// ---------------------------------------------------------------------------
#define FA_QH 0
#define FA_QL 17408
#define FA_KH 34816
#define FA_KL 52224
#define FA_VH 69632
#define FA_VL 88064
#define FA_SMEM 106496

__global__ __launch_bounds__(128) void flash_attn() {
    extern __shared__ char smem[];
    const uint32_t sb = smem_u32(smem);

    const int qb   = blockIdx.x;
    const int h    = blockIdx.y;
    const int kvh  = h >> 2;
    const int q0   = qb * 64;
    const int tid  = threadIdx.x;
    const int lane = tid & 31;
    const int w    = tid >> 5;

#pragma unroll
    for (int i = 0; i < 8; i++) {
        int idx = tid + 128 * i;
        int r = idx >> 4;
        int c = (idx & 15) * 8;
        uint32_t so = (uint32_t)(r * 272 + (idx & 15) * 16);
        CP_ASYNC16(sb + FA_QH + so, g_qh + (long long)(q0 + r) * DMODEL + h * HD + c);
        CP_ASYNC16(sb + FA_QL + so, g_ql + (long long)(q0 + r) * DMODEL + h * HD + c);
    }
    CP_COMMIT();

    float out[16][4];
#pragma unroll
    for (int i = 0; i < 16; i++)
#pragma unroll
        for (int e = 0; e < 4; e++) out[i][e] = 0.f;
    float m0 = -1e30f, m1 = -1e30f, l0 = 0.f, l1 = 0.f;

    for (int kt = 0; kt < S_LEN / 64; kt++) {
        const int s0 = kt * 64;
        __syncthreads();
#pragma unroll
        for (int i = 0; i < 8; i++) {
            int idx = tid + 128 * i;
            int r = idx >> 4;
            int c = (idx & 15) * 8;
            uint32_t so = (uint32_t)(r * 272 + (idx & 15) * 16);
            CP_ASYNC16(sb + FA_KH + so, g_kh + (long long)(s0 + r) * DKV + kvh * HD + c);
            CP_ASYNC16(sb + FA_KL + so, g_kl + (long long)(s0 + r) * DKV + kvh * HD + c);
        }
#pragma unroll
        for (int i = 0; i < 8; i++) {
            int idx = tid + 128 * i;
            int r = idx >> 3;
            int c = (idx & 7) * 8;
            uint32_t so = (uint32_t)(r * 144 + (idx & 7) * 16);
            CP_ASYNC16(sb + FA_VH + so, g_vth + (long long)(kvh * HD + r) * S_LEN + s0 + c);
            CP_ASYNC16(sb + FA_VL + so, g_vtl + (long long)(kvh * HD + r) * S_LEN + s0 + c);
        }
        CP_COMMIT();
        CP_WAIT0();
        __syncthreads();

        float s_acc[8][4];
#pragma unroll
        for (int nj = 0; nj < 8; nj++)
#pragma unroll
            for (int e = 0; e < 4; e++) s_acc[nj][e] = 0.f;

#pragma unroll
        for (int kc = 0; kc < 8; kc++) {
            uint32_t qa_h[4], qa_l[4];
            {
                int rr = lane & 15;
                int cc = kc * 16 + ((lane >> 4) << 3);
                uint32_t off = (uint32_t)((w * 16 + rr) * 272 + cc * 2);
                ldsm_x4(qa_h, sb + FA_QH + off);
                ldsm_x4(qa_l, sb + FA_QL + off);
            }
            int rr    = lane & 7;
            int cc    = kc * 16 + (((lane >> 3) & 1) << 3);
            int njoff = (lane >> 4) << 3;
#pragma unroll
            for (int njp = 0; njp < 4; njp++) {
                uint32_t bh4[4], bl4[4];
                uint32_t off = (uint32_t)((njp * 16 + njoff + rr) * 272 + cc * 2);
                ldsm_x4(bh4, sb + FA_KH + off);
                ldsm_x4(bl4, sb + FA_KL + off);
                mma_bf16(s_acc[2 * njp], qa_h, bh4);
                mma_bf16(s_acc[2 * njp], qa_h, bl4);
                mma_bf16(s_acc[2 * njp], qa_l, bh4);
                mma_bf16(s_acc[2 * njp + 1], qa_h, bh4 + 2);
                mma_bf16(s_acc[2 * njp + 1], qa_h, bl4 + 2);
                mma_bf16(s_acc[2 * njp + 1], qa_l, bh4 + 2);
            }
        }

        float mt0 = -1e30f, mt1 = -1e30f;
#pragma unroll
        for (int nj = 0; nj < 8; nj++) {
            mt0 = fmaxf(mt0, fmaxf(s_acc[nj][0], s_acc[nj][1]));
            mt1 = fmaxf(mt1, fmaxf(s_acc[nj][2], s_acc[nj][3]));
        }
        mt0 = fmaxf(mt0, __shfl_xor_sync(0xffffffffu, mt0, 1));
        mt0 = fmaxf(mt0, __shfl_xor_sync(0xffffffffu, mt0, 2));
        mt1 = fmaxf(mt1, __shfl_xor_sync(0xffffffffu, mt1, 1));
        mt1 = fmaxf(mt1, __shfl_xor_sync(0xffffffffu, mt1, 2));

        float mn0 = fmaxf(m0, mt0), mn1 = fmaxf(m1, mt1);
        float a0 = __expf(m0 - mn0), a1 = __expf(m1 - mn1);
        float sum0 = 0.f, sum1 = 0.f;
#pragma unroll
        for (int nj = 0; nj < 8; nj++) {
            s_acc[nj][0] = __expf(s_acc[nj][0] - mn0);
            s_acc[nj][1] = __expf(s_acc[nj][1] - mn0);
            s_acc[nj][2] = __expf(s_acc[nj][2] - mn1);
            s_acc[nj][3] = __expf(s_acc[nj][3] - mn1);
            sum0 += s_acc[nj][0] + s_acc[nj][1];
            sum1 += s_acc[nj][2] + s_acc[nj][3];
        }
        sum0 += __shfl_xor_sync(0xffffffffu, sum0, 1);
        sum0 += __shfl_xor_sync(0xffffffffu, sum0, 2);
        sum1 += __shfl_xor_sync(0xffffffffu, sum1, 1);
        sum1 += __shfl_xor_sync(0xffffffffu, sum1, 2);
        l0 = l0 * a0 + sum0;  m0 = mn0;
        l1 = l1 * a1 + sum1;  m1 = mn1;
#pragma unroll
        for (int i = 0; i < 16; i++) {
            out[i][0] *= a0; out[i][1] *= a0;
            out[i][2] *= a1; out[i][3] *= a1;
        }

#pragma unroll
        for (int kc = 0; kc < 4; kc++) {
            uint32_t pah[4], pal[4];
            {
                __nv_bfloat16 h0, h1, lo0, lo1;
                split2(s_acc[2 * kc][0], h0, lo0); split2(s_acc[2 * kc][1], h1, lo1);
                pah[0] = packpair(h0, h1); pal[0] = packpair(lo0, lo1);
                split2(s_acc[2 * kc][2], h0, lo0); split2(s_acc[2 * kc][3], h1, lo1);
                pah[1] = packpair(h0, h1); pal[1] = packpair(lo0, lo1);
                split2(s_acc[2 * kc + 1][0], h0, lo0); split2(s_acc[2 * kc + 1][1], h1, lo1);
                pah[2] = packpair(h0, h1); pal[2] = packpair(lo0, lo1);
                split2(s_acc[2 * kc + 1][2], h0, lo0); split2(s_acc[2 * kc + 1][3], h1, lo1);
                pah[3] = packpair(h0, h1); pal[3] = packpair(lo0, lo1);
            }
            int rr    = lane & 7;
            int cc    = kc * 16 + (((lane >> 3) & 1) << 3);
            int ndoff = (lane >> 4) << 3;
#pragma unroll
            for (int ndp = 0; ndp < 8; ndp++) {
                uint32_t vh4[4], vl4[4];
                uint32_t off = (uint32_t)((ndp * 16 + ndoff + rr) * 144 + cc * 2);
                ldsm_x4(vh4, sb + FA_VH + off);
                ldsm_x4(vl4, sb + FA_VL + off);
                mma_bf16(out[2 * ndp], pah, vh4);
                mma_bf16(out[2 * ndp], pah, vl4);
                mma_bf16(out[2 * ndp], pal, vh4);
                mma_bf16(out[2 * ndp + 1], pah, vh4 + 2);
                mma_bf16(out[2 * ndp + 1], pah, vl4 + 2);
                mma_bf16(out[2 * ndp + 1], pal, vh4 + 2);
            }
        }
    }

    float inv0 = 1.0f / l0, inv1 = 1.0f / l1;
    int row0 = q0 + w * 16 + (lane >> 2);
    int row1 = row0 + 8;
#pragma unroll
    for (int nd = 0; nd < 16; nd++) {
        int col = h * HD + nd * 8 + (lane & 3) * 2;
        __nv_bfloat16 h0, h1, lo0, lo1;
        split2(out[nd][0] * inv0, h0, lo0);
        split2(out[nd][1] * inv0, h1, lo1);
        *(uint32_t*)(g_ah + (size_t)row0 * DMODEL + col) = packpair(h0, h1);
        *(uint32_t*)(g_al + (size_t)row0 * DMODEL + col) = packpair(lo0, lo1);
        split2(out[nd][2] * inv1, h0, lo0);
        split2(out[nd][3] * inv1, h1, lo1);
        *(uint32_t*)(g_ah + (size_t)row1 * DMODEL + col) = packpair(h0, h1);
        *(uint32_t*)(g_al + (size_t)row1 * DMODEL + col) = packpair(lo0, lo1);
    }
}

// ---------------------------------------------------------------------------
// Split: fp32 -> bf16 hi/lo, MLP=4 grid-stride
// ---------------------------------------------------------------------------
__global__ void split_f32(const float* __restrict__ in,
                          __nv_bfloat16* __restrict__ hi,
                          __nv_bfloat16* __restrict__ lo, int n4)
{
    const int stride = gridDim.x * blockDim.x;
    const int i0 = blockIdx.x * blockDim.x + threadIdx.x;
    float4 v[4]; int idx[4]; int cnt = 0;
#pragma unroll
    for (int u = 0; u < 4; u++) {
        int j = i0 + u * stride;
        if (j < n4) { idx[cnt] = j; v[cnt] = ((const float4*)in)[j]; cnt++; }
    }
#pragma unroll 4
    for (int t = 0; t < cnt; t++) {
        __nv_bfloat16 h0, h1, h2, h3, l0, l1, l2, l3;
        split2(v[t].x, h0, l0); split2(v[t].y, h1, l1);
        split2(v[t].z, h2, l2); split2(v[t].w, h3, l3);
        ((uint2*)hi)[idx[t]] = make_uint2(packpair(h0, h1), packpair(h2, h3));
        ((uint2*)lo)[idx[t]] = make_uint2(packpair(l0, l1), packpair(l2, l3));
    }
}

// ---------------------------------------------------------------------------
// Transpose V [s][d] -> Vt [d][s], bf16 hi/lo
// ---------------------------------------------------------------------------
__global__ void transpose_v_split() {
    __shared__ float t[32][33];
    int d0 = blockIdx.x * 32;
    int s0 = blockIdx.y * 32;
    for (int i = threadIdx.y; i < 32; i += 8)
        t[i][threadIdx.x] = g_v[(size_t)(s0 + i) * DKV + d0 + threadIdx.x];
    __syncthreads();
    for (int i = threadIdx.y; i < 32; i += 8) {
        float v = t[threadIdx.x][i];
        __nv_bfloat16 h, l;
        split2(v, h, l);
        size_t o = (size_t)(d0 + i) * S_LEN + s0 + threadIdx.x;
        g_vth[o] = h;
        g_vtl[o] = l;
    }
}

// ---------------------------------------------------------------------------
// Launch
// ---------------------------------------------------------------------------
extern "C" void kernel_launch(void* const* d_in, const int* in_sizes, int n_in,
                              void* d_out, int out_size)
{
    const float* x  = (const float*)d_in[0];
    const float* wq = (const float*)d_in[1];
    const float* wk = (const float*)d_in[2];
    const float* wv = (const float*)d_in[3];
    const float* wo = (const float*)d_in[4];
    float* out = (float*)d_out;

    __nv_bfloat16 *xh, *xl, *wqh, *wql, *wkh, *wkl, *wvh, *wvl, *woh, *wol, *ah, *al;
    cudaGetSymbolAddress((void**)&xh,  g_xh);  cudaGetSymbolAddress((void**)&xl,  g_xl);
    cudaGetSymbolAddress((void**)&wqh, g_wqh); cudaGetSymbolAddress((void**)&wql, g_wql);
    cudaGetSymbolAddress((void**)&wkh, g_wkh); cudaGetSymbolAddress((void**)&wkl, g_wkl);
    cudaGetSymbolAddress((void**)&wvh, g_wvh); cudaGetSymbolAddress((void**)&wvl, g_wvl);
    cudaGetSymbolAddress((void**)&woh, g_woh); cudaGetSymbolAddress((void**)&wol, g_wol);
    cudaGetSymbolAddress((void**)&ah,  g_ah);  cudaGetSymbolAddress((void**)&al,  g_al);

    cudaFuncSetAttribute(tcg_nt,
        cudaFuncAttributeMaxDynamicSharedMemorySize, GSMEM);
    cudaFuncSetAttribute(tcg_qkv,
        cudaFuncAttributeMaxDynamicSharedMemorySize, GSMEM);
    cudaFuncSetAttribute(flash_attn,
        cudaFuncAttributeMaxDynamicSharedMemorySize, FA_SMEM);

#define SPLIT(src, h, l, n) do {                                    \
    int n4 = (int)((n) / 4);                                        \
    int blocks = (n4 + 4 * 256 - 1) / (4 * 256);                    \
    split_f32<<<blocks, 256>>>(src, h, l, n4);                      \
} while (0)

    // 0) tables + split inputs
    init_tables<<<S_LEN, 64>>>();
    SPLIT(x,  xh,  xl,  (long long)S_LEN * DMODEL);
    SPLIT(wq, wqh, wql, (long long)DMODEL * DMODEL);
    SPLIT(wk, wkh, wkl, (long long)DKV * DMODEL);
    SPLIT(wv, wvh, wvl, (long long)DKV * DMODEL);
    SPLIT(wo, woh, wol, (long long)DMODEL * DMODEL);

    // 1) Merged Q/K/V projections with fused RoPE (Q pre-scaled)
    tcg_qkv<<<dim3(48, 16), 256, GSMEM>>>();

    // 2) V transpose -> bf16 hi/lo Vt
    transpose_v_split<<<dim3(DKV / 32, S_LEN / 32), dim3(32, 8)>>>();

    // 3) Fused attention -> g_ah/g_al
    flash_attn<<<dim3(S_LEN / 64, HQ), 128, FA_SMEM>>>();

    // 4) out = attn * wo^T
    tcg_nt<<<dim3(DMODEL / 128, S_LEN / 128), 256, GSMEM>>>(
        ah, al, woh, wol, out, DMODEL, DMODEL, DMODEL, DMODEL);
}

// round 12
// speedup vs baseline: 1.0670x; 1.0670x over previous
#include <cuda_runtime.h>
#include <cuda_bf16.h>
#include <cstdint>
#include <math.h>

// Problem constants
#define S_LEN  2048
#define DMODEL 4096
#define HQ     32
#define HKV    8
#define HD     128
#define DKV    (HKV * HD)   // 1024

// ---------------------------------------------------------------------------
// Scratch (device globals)
// ---------------------------------------------------------------------------
__device__ float g_q[(size_t)S_LEN * DMODEL];       // fp32 Q projection
__device__ float g_k[(size_t)S_LEN * DKV];          // fp32 K projection
__device__ float g_v[(size_t)S_LEN * DKV];          // fp32 V projection

__device__ __nv_bfloat16 g_xh[(size_t)S_LEN * DMODEL],  g_xl[(size_t)S_LEN * DMODEL];
__device__ __nv_bfloat16 g_wqh[(size_t)DMODEL * DMODEL], g_wql[(size_t)DMODEL * DMODEL];
__device__ __nv_bfloat16 g_wkh[(size_t)DKV * DMODEL],    g_wkl[(size_t)DKV * DMODEL];
__device__ __nv_bfloat16 g_wvh[(size_t)DKV * DMODEL],    g_wvl[(size_t)DKV * DMODEL];
__device__ __nv_bfloat16 g_woh[(size_t)DMODEL * DMODEL], g_wol[(size_t)DMODEL * DMODEL];
__device__ __nv_bfloat16 g_qh[(size_t)S_LEN * DMODEL],   g_ql[(size_t)S_LEN * DMODEL];
__device__ __nv_bfloat16 g_kh[(size_t)S_LEN * DKV],      g_kl[(size_t)S_LEN * DKV];
__device__ __nv_bfloat16 g_vth[(size_t)DKV * S_LEN],     g_vtl[(size_t)DKV * S_LEN];
__device__ __nv_bfloat16 g_ah[(size_t)S_LEN * DMODEL],   g_al[(size_t)S_LEN * DMODEL];

// ---------------------------------------------------------------------------
// PTX helpers
// ---------------------------------------------------------------------------
__device__ __forceinline__ uint32_t smem_u32(const void* p) {
    uint32_t a;
    asm("{ .reg .u64 t; cvta.to.shared.u64 t, %1; cvt.u32.u64 %0, t; }"
        : "=r"(a) : "l"(p));
    return a;
}
__device__ __forceinline__ void ldsm_x4(uint32_t r[4], uint32_t addr) {
    asm volatile("ldmatrix.sync.aligned.m8n8.x4.shared.b16 {%0,%1,%2,%3}, [%4];"
        : "=r"(r[0]), "=r"(r[1]), "=r"(r[2]), "=r"(r[3]) : "r"(addr));
}
__device__ __forceinline__ void mma_bf16(float d[4], const uint32_t a[4],
                                         const uint32_t b[2]) {
    asm volatile(
        "mma.sync.aligned.m16n8k16.row.col.f32.bf16.bf16.f32 "
        "{%0,%1,%2,%3}, {%4,%5,%6,%7}, {%8,%9}, {%0,%1,%2,%3};"
        : "+f"(d[0]), "+f"(d[1]), "+f"(d[2]), "+f"(d[3])
        : "r"(a[0]), "r"(a[1]), "r"(a[2]), "r"(a[3]), "r"(b[0]), "r"(b[1]));
}
#define CP_ASYNC16(sm_addr, gptr) \
    asm volatile("cp.async.cg.shared.global [%0], [%1], 16;" \
                 :: "r"(sm_addr), "l"(gptr) : "memory")
#define CP_COMMIT() asm volatile("cp.async.commit_group;" ::: "memory")
#define CP_WAIT0()  asm volatile("cp.async.wait_group 0;" ::: "memory")
#define CP_WAIT1()  asm volatile("cp.async.wait_group 1;" ::: "memory")

__device__ __forceinline__ void split2(float x, __nv_bfloat16& h, __nv_bfloat16& l) {
    h = __float2bfloat16(x);
    l = __float2bfloat16(x - __bfloat162float(h));
}
__device__ __forceinline__ uint32_t packpair(__nv_bfloat16 a, __nv_bfloat16 b) {
    __nv_bfloat162 t = __halves2bfloat162(a, b);
    return *reinterpret_cast<uint32_t*>(&t);
}

// ---------------------------------------------------------------------------
// Shared GEMM core (proven R8): C = (Ah+Al)(Bh+Bl)^T, 128x128 tile, 256 thr
// ---------------------------------------------------------------------------
#define TILE_B (128 * 80)
#define STAGE_B (4 * TILE_B)
#define GSMEM  (2 * STAGE_B)

__device__ __forceinline__ void gemm_core(
    const __nv_bfloat16* __restrict__ Ah, const __nv_bfloat16* __restrict__ Al,
    const __nv_bfloat16* __restrict__ Bh, const __nv_bfloat16* __restrict__ Bl,
    float* __restrict__ C, int K, int lda, int ldb, int ldc,
    int row0, int col0, char* smem)
{
    const uint32_t sbase = smem_u32(smem);
    const int tid  = threadIdx.x;
    const int lane = tid & 31;
    const int w    = tid >> 5;
    const int wm   = (w & 1) * 64;
    const int wn   = (w >> 1) * 32;

    const int pr  = (tid << 1) >> 2;
    const int pr1 = ((tid << 1) + 1) >> 2;
    const int pc  = ((tid << 1) & 3) * 8;
    const int pc1 = (((tid << 1) + 1) & 3) * 8;

    float acc[4][4][4];
#pragma unroll
    for (int i = 0; i < 4; i++)
#pragma unroll
        for (int j = 0; j < 4; j++)
#pragma unroll
            for (int e = 0; e < 4; e++) acc[i][j][e] = 0.f;

    const int KT = K / 32;

#define PREFETCH(kt, stage) do {                                               \
    const int k0 = (kt) * 32;                                                  \
    const uint32_t ss = sbase + (stage) * STAGE_B;                             \
    uint32_t o0 = (uint32_t)(pr  * 80 + pc  * 2);                              \
    uint32_t o1 = (uint32_t)(pr1 * 80 + pc1 * 2);                              \
    CP_ASYNC16(ss + o0,              Ah + (long long)(row0 + pr ) * lda + k0 + pc ); \
    CP_ASYNC16(ss + o1,              Ah + (long long)(row0 + pr1) * lda + k0 + pc1); \
    CP_ASYNC16(ss + TILE_B + o0,     Al + (long long)(row0 + pr ) * lda + k0 + pc ); \
    CP_ASYNC16(ss + TILE_B + o1,     Al + (long long)(row0 + pr1) * lda + k0 + pc1); \
    CP_ASYNC16(ss + 2 * TILE_B + o0, Bh + (long long)(col0 + pr ) * ldb + k0 + pc ); \
    CP_ASYNC16(ss + 2 * TILE_B + o1, Bh + (long long)(col0 + pr1) * ldb + k0 + pc1); \
    CP_ASYNC16(ss + 3 * TILE_B + o0, Bl + (long long)(col0 + pr ) * ldb + k0 + pc ); \
    CP_ASYNC16(ss + 3 * TILE_B + o1, Bl + (long long)(col0 + pr1) * ldb + k0 + pc1); \
} while (0)

    PREFETCH(0, 0);
    CP_COMMIT();

    for (int kt = 0; kt < KT; kt++) {
        CP_WAIT0();
        __syncthreads();
        if (kt + 1 < KT) {
            PREFETCH(kt + 1, (kt + 1) & 1);
            CP_COMMIT();
        }
        const uint32_t ss = sbase + (kt & 1) * STAGE_B;
        const uint32_t ah0 = ss, al0 = ss + TILE_B;
        const uint32_t bh0 = ss + 2 * TILE_B, bl0 = ss + 3 * TILE_B;

#pragma unroll
        for (int kc = 0; kc < 2; kc++) {
            const int kb = kc * 16;
            uint32_t afh[4][4], afl[4][4];
            {
                int rr = lane & 15;
                int cc = kb + ((lane >> 4) << 3);
#pragma unroll
                for (int mi = 0; mi < 4; mi++) {
                    uint32_t off = (uint32_t)((wm + mi * 16 + rr) * 80 + cc * 2);
                    ldsm_x4(afh[mi], ah0 + off);
                    ldsm_x4(afl[mi], al0 + off);
                }
            }
            {
                int rr    = lane & 7;
                int cc    = kb + (((lane >> 3) & 1) << 3);
                int njoff = (lane >> 4) << 3;
#pragma unroll
                for (int njp = 0; njp < 2; njp++) {
                    uint32_t bh4[4], bl4[4];
                    uint32_t off = (uint32_t)((wn + njp * 16 + njoff + rr) * 80 + cc * 2);
                    ldsm_x4(bh4, bh0 + off);
                    ldsm_x4(bl4, bl0 + off);
#pragma unroll
                    for (int mi = 0; mi < 4; mi++) {
                        mma_bf16(acc[mi][2 * njp], afh[mi], bh4);
                        mma_bf16(acc[mi][2 * njp], afh[mi], bl4);
                        mma_bf16(acc[mi][2 * njp], afl[mi], bh4);
                        mma_bf16(acc[mi][2 * njp + 1], afh[mi], bh4 + 2);
                        mma_bf16(acc[mi][2 * njp + 1], afh[mi], bl4 + 2);
                        mma_bf16(acc[mi][2 * njp + 1], afl[mi], bh4 + 2);
                    }
                }
            }
        }
        __syncthreads();
    }
#undef PREFETCH

#pragma unroll
    for (int mi = 0; mi < 4; mi++)
#pragma unroll
        for (int nj = 0; nj < 4; nj++) {
            int r = row0 + wm + mi * 16 + (lane >> 2);
            int c = col0 + wn + nj * 8 + (lane & 3) * 2;
            float* p0 = C + (long long)r * ldc + c;
            p0[0] = acc[mi][nj][0];
            p0[1] = acc[mi][nj][1];
            float* p1 = C + (long long)(r + 8) * ldc + c;
            p1[0] = acc[mi][nj][2];
            p1[1] = acc[mi][nj][3];
        }
}

// Merged Q/K/V projection: grid (48, 16)
__global__ __launch_bounds__(256) void tcg_qkv() {
    extern __shared__ char smem[];
    const int cb = blockIdx.x;
    const __nv_bfloat16 *Bh, *Bl; float* C; int ldc, col0;
    if (cb < 32)      { Bh = g_wqh; Bl = g_wql; C = g_q; ldc = DMODEL; col0 = cb * 128; }
    else if (cb < 40) { Bh = g_wkh; Bl = g_wkl; C = g_k; ldc = DKV;    col0 = (cb - 32) * 128; }
    else              { Bh = g_wvh; Bl = g_wvl; C = g_v; ldc = DKV;    col0 = (cb - 40) * 128; }
    gemm_core(g_xh, g_xl, Bh, Bl, C, DMODEL, DMODEL, DMODEL, ldc,
              blockIdx.y * 128, col0, smem);
}

// Generic NT GEMM (wo)
__global__ __launch_bounds__(256) void tcg_nt(
    const __nv_bfloat16* __restrict__ Ah, const __nv_bfloat16* __restrict__ Al,
    const __nv_bfloat16* __restrict__ Bh, const __nv_bfloat16* __restrict__ Bl,
    float* __restrict__ C, int K, int lda, int ldb, int ldc)
{
    extern __shared__ char smem[];
    gemm_core(Ah, Al, Bh, Bl, C, K, lda, ldb, ldc,
              blockIdx.y * 128, blockIdx.x * 128, smem);
}

// ---------------------------------------------------------------------------
// Flash attention v2: q-tile 128, k-tile 64, 256 threads (8 warps x 16 rows),
// double-buffered K/V stages. bf16 hi/lo in/out. Q pre-scaled by 1/sqrt(128).
// ---------------------------------------------------------------------------
#define FB_QH 0
#define FB_QL 34816
#define FB_K(st) (69632 + (st) * 34816)    // KH +0, KL +17408 within stage
#define FB_V(st) (139264 + (st) * 36864)   // VH +0, VL +18432 within stage
#define FB_SMEM 212992

__global__ __launch_bounds__(256) void flash_attn2() {
    extern __shared__ char smem[];
    const uint32_t sb = smem_u32(smem);

    const int qb   = blockIdx.x;          // 0..15 (128 q-rows each)
    const int h    = blockIdx.y;          // head
    const int kvh  = h >> 2;
    const int q0   = qb * 128;
    const int tid  = threadIdx.x;
    const int lane = tid & 31;
    const int w    = tid >> 5;            // 0..7

    // ---- Q tile (128 x 128 bf16 hi/lo), loaded once ----
#pragma unroll
    for (int i = 0; i < 8; i++) {
        int idx = tid + 256 * i;          // 0..2047
        int r = idx >> 4;                 // 0..127
        int ck = idx & 15;
        uint32_t so = (uint32_t)(r * 272 + ck * 16);
        CP_ASYNC16(sb + FB_QH + so, g_qh + (long long)(q0 + r) * DMODEL + h * HD + ck * 8);
        CP_ASYNC16(sb + FB_QL + so, g_ql + (long long)(q0 + r) * DMODEL + h * HD + ck * 8);
    }
    CP_COMMIT();

#define FB_PREFETCH(kt, st) do {                                              \
    const int s0_ = (kt) * 64;                                                \
    const uint32_t kb_ = sb + FB_K(st);                                       \
    const uint32_t vb_ = sb + FB_V(st);                                       \
    _Pragma("unroll")                                                         \
    for (int i_ = 0; i_ < 4; i_++) {                                          \
        int idx_ = tid + 256 * i_;                                            \
        int r_ = idx_ >> 4;                                                   \
        int ck_ = idx_ & 15;                                                  \
        uint32_t so_ = (uint32_t)(r_ * 272 + ck_ * 16);                       \
        CP_ASYNC16(kb_ + so_,         g_kh + (long long)(s0_ + r_) * DKV + kvh * HD + ck_ * 8); \
        CP_ASYNC16(kb_ + 17408 + so_, g_kl + (long long)(s0_ + r_) * DKV + kvh * HD + ck_ * 8); \
    }                                                                         \
    _Pragma("unroll")                                                         \
    for (int i_ = 0; i_ < 4; i_++) {                                          \
        int idx_ = tid + 256 * i_;                                            \
        int r_ = idx_ >> 3;                                                   \
        int ck_ = idx_ & 7;                                                   \
        uint32_t so_ = (uint32_t)(r_ * 144 + ck_ * 16);                       \
        CP_ASYNC16(vb_ + so_,         g_vth + (long long)(kvh * HD + r_) * S_LEN + s0_ + ck_ * 8); \
        CP_ASYNC16(vb_ + 18432 + so_, g_vtl + (long long)(kvh * HD + r_) * S_LEN + s0_ + ck_ * 8); \
    }                                                                         \
} while (0)

    FB_PREFETCH(0, 0);
    CP_COMMIT();

    float out[16][4];
#pragma unroll
    for (int i = 0; i < 16; i++)
#pragma unroll
        for (int e = 0; e < 4; e++) out[i][e] = 0.f;
    float m0 = -1e30f, m1 = -1e30f, l0 = 0.f, l1 = 0.f;

    for (int kt = 0; kt < S_LEN / 64; kt++) {
        if (kt + 1 < S_LEN / 64) {
            FB_PREFETCH(kt + 1, (kt + 1) & 1);
            CP_COMMIT();
            CP_WAIT1();          // current stage (and Q) arrived; next in flight
        } else {
            CP_WAIT0();
        }
        __syncthreads();

        const uint32_t kh0 = sb + FB_K(kt & 1);
        const uint32_t kl0 = kh0 + 17408;
        const uint32_t vh0 = sb + FB_V(kt & 1);
        const uint32_t vl0 = vh0 + 18432;

        // ---- QK^T: 16 q-rows (this warp) x 64 k-cols ----
        float s_acc[8][4];
#pragma unroll
        for (int nj = 0; nj < 8; nj++)
#pragma unroll
            for (int e = 0; e < 4; e++) s_acc[nj][e] = 0.f;

#pragma unroll
        for (int kc = 0; kc < 8; kc++) {
            uint32_t qa_h[4], qa_l[4];
            {
                int rr = lane & 15;
                int cc = kc * 16 + ((lane >> 4) << 3);
                uint32_t off = (uint32_t)((w * 16 + rr) * 272 + cc * 2);
                ldsm_x4(qa_h, sb + FB_QH + off);
                ldsm_x4(qa_l, sb + FB_QL + off);
            }
            int rr    = lane & 7;
            int cc    = kc * 16 + (((lane >> 3) & 1) << 3);
            int njoff = (lane >> 4) << 3;
#pragma unroll
            for (int njp = 0; njp < 4; njp++) {
                uint32_t bh4[4], bl4[4];
                uint32_t off = (uint32_t)((njp * 16 + njoff + rr) * 272 + cc * 2);
                ldsm_x4(bh4, kh0 + off);
                ldsm_x4(bl4, kl0 + off);
                mma_bf16(s_acc[2 * njp], qa_h, bh4);
                mma_bf16(s_acc[2 * njp], qa_h, bl4);
                mma_bf16(s_acc[2 * njp], qa_l, bh4);
                mma_bf16(s_acc[2 * njp + 1], qa_h, bh4 + 2);
                mma_bf16(s_acc[2 * njp + 1], qa_h, bl4 + 2);
                mma_bf16(s_acc[2 * njp + 1], qa_l, bh4 + 2);
            }
        }

        // ---- online softmax (rows warp-local) ----
        float mt0 = -1e30f, mt1 = -1e30f;
#pragma unroll
        for (int nj = 0; nj < 8; nj++) {
            mt0 = fmaxf(mt0, fmaxf(s_acc[nj][0], s_acc[nj][1]));
            mt1 = fmaxf(mt1, fmaxf(s_acc[nj][2], s_acc[nj][3]));
        }
        mt0 = fmaxf(mt0, __shfl_xor_sync(0xffffffffu, mt0, 1));
        mt0 = fmaxf(mt0, __shfl_xor_sync(0xffffffffu, mt0, 2));
        mt1 = fmaxf(mt1, __shfl_xor_sync(0xffffffffu, mt1, 1));
        mt1 = fmaxf(mt1, __shfl_xor_sync(0xffffffffu, mt1, 2));

        float mn0 = fmaxf(m0, mt0), mn1 = fmaxf(m1, mt1);
        float a0 = __expf(m0 - mn0), a1 = __expf(m1 - mn1);
        float sum0 = 0.f, sum1 = 0.f;
#pragma unroll
        for (int nj = 0; nj < 8; nj++) {
            s_acc[nj][0] = __expf(s_acc[nj][0] - mn0);
            s_acc[nj][1] = __expf(s_acc[nj][1] - mn0);
            s_acc[nj][2] = __expf(s_acc[nj][2] - mn1);
            s_acc[nj][3] = __expf(s_acc[nj][3] - mn1);
            sum0 += s_acc[nj][0] + s_acc[nj][1];
            sum1 += s_acc[nj][2] + s_acc[nj][3];
        }
        sum0 += __shfl_xor_sync(0xffffffffu, sum0, 1);
        sum0 += __shfl_xor_sync(0xffffffffu, sum0, 2);
        sum1 += __shfl_xor_sync(0xffffffffu, sum1, 1);
        sum1 += __shfl_xor_sync(0xffffffffu, sum1, 2);
        l0 = l0 * a0 + sum0;  m0 = mn0;
        l1 = l1 * a1 + sum1;  m1 = mn1;
#pragma unroll
        for (int i = 0; i < 16; i++) {
            out[i][0] *= a0; out[i][1] *= a0;
            out[i][2] *= a1; out[i][3] *= a1;
        }

        // ---- PV ----
#pragma unroll
        for (int kc = 0; kc < 4; kc++) {
            uint32_t pah[4], pal[4];
            {
                __nv_bfloat16 h0, h1, lo0, lo1;
                split2(s_acc[2 * kc][0], h0, lo0); split2(s_acc[2 * kc][1], h1, lo1);
                pah[0] = packpair(h0, h1); pal[0] = packpair(lo0, lo1);
                split2(s_acc[2 * kc][2], h0, lo0); split2(s_acc[2 * kc][3], h1, lo1);
                pah[1] = packpair(h0, h1); pal[1] = packpair(lo0, lo1);
                split2(s_acc[2 * kc + 1][0], h0, lo0); split2(s_acc[2 * kc + 1][1], h1, lo1);
                pah[2] = packpair(h0, h1); pal[2] = packpair(lo0, lo1);
                split2(s_acc[2 * kc + 1][2], h0, lo0); split2(s_acc[2 * kc + 1][3], h1, lo1);
                pah[3] = packpair(h0, h1); pal[3] = packpair(lo0, lo1);
            }
            int rr    = lane & 7;
            int cc    = kc * 16 + (((lane >> 3) & 1) << 3);
            int ndoff = (lane >> 4) << 3;
#pragma unroll
            for (int ndp = 0; ndp < 8; ndp++) {
                uint32_t vh4[4], vl4[4];
                uint32_t off = (uint32_t)((ndp * 16 + ndoff + rr) * 144 + cc * 2);
                ldsm_x4(vh4, vh0 + off);
                ldsm_x4(vl4, vl0 + off);
                mma_bf16(out[2 * ndp], pah, vh4);
                mma_bf16(out[2 * ndp], pah, vl4);
                mma_bf16(out[2 * ndp], pal, vh4);
                mma_bf16(out[2 * ndp + 1], pah, vh4 + 2);
                mma_bf16(out[2 * ndp + 1], pah, vl4 + 2);
                mma_bf16(out[2 * ndp + 1], pal, vh4 + 2);
            }
        }
        __syncthreads();   // all reads of this stage done before it is overwritten
    }

    // ---- epilogue ----
    float inv0 = 1.0f / l0, inv1 = 1.0f / l1;
    int row0 = q0 + w * 16 + (lane >> 2);
    int row1 = row0 + 8;
#pragma unroll
    for (int nd = 0; nd < 16; nd++) {
        int col = h * HD + nd * 8 + (lane & 3) * 2;
        __nv_bfloat16 h0, h1, lo0, lo1;
        split2(out[nd][0] * inv0, h0, lo0);
        split2(out[nd][1] * inv0, h1, lo1);
        *(uint32_t*)(g_ah + (size_t)row0 * DMODEL + col) = packpair(h0, h1);
        *(uint32_t*)(g_al + (size_t)row0 * DMODEL + col) = packpair(lo0, lo1);
        split2(out[nd][2] * inv1, h0, lo0);
        split2(out[nd][3] * inv1, h1, lo1);
        *(uint32_t*)(g_ah + (size_t)row1 * DMODEL + col) = packpair(h0, h1);
        *(uint32_t*)(g_al + (size_t)row1 * DMODEL + col) = packpair(lo0, lo1);
    }
}

// ---------------------------------------------------------------------------
// Split: fp32 -> bf16 hi/lo, MLP=4 grid-stride
// ---------------------------------------------------------------------------
__global__ void split_f32(const float* __restrict__ in,
                          __nv_bfloat16* __restrict__ hi,
                          __nv_bfloat16* __restrict__ lo, int n4)
{
    const int stride = gridDim.x * blockDim.x;
    const int i0 = blockIdx.x * blockDim.x + threadIdx.x;
    float4 v[4]; int idx[4]; int cnt = 0;
#pragma unroll
    for (int u = 0; u < 4; u++) {
        int j = i0 + u * stride;
        if (j < n4) { idx[cnt] = j; v[cnt] = ((const float4*)in)[j]; cnt++; }
    }
#pragma unroll 4
    for (int t = 0; t < cnt; t++) {
        __nv_bfloat16 h0, h1, h2, h3, l0, l1, l2, l3;
        split2(v[t].x, h0, l0); split2(v[t].y, h1, l1);
        split2(v[t].z, h2, l2); split2(v[t].w, h3, l3);
        ((uint2*)hi)[idx[t]] = make_uint2(packpair(h0, h1), packpair(h2, h3));
        ((uint2*)lo)[idx[t]] = make_uint2(packpair(l0, l1), packpair(l2, l3));
    }
}

// ---------------------------------------------------------------------------
// RoPE: fp32 in, bf16 hi/lo out; Q pre-scaled by 1/sqrt(128)
// ---------------------------------------------------------------------------
__global__ void rope_split() {
    long long idx = (long long)blockIdx.x * blockDim.x + threadIdx.x;
    const long long QP = (long long)S_LEN * HQ * 64;
    const long long KP = (long long)S_LEN * HKV * 64;
    if (idx >= QP + KP) return;

    const float* src; __nv_bfloat16 *dh, *dl;
    int s, h, i, stride; float postscale;
    if (idx < QP) {
        s = (int)(idx / (HQ * 64));
        int rem = (int)(idx % (HQ * 64));
        h = rem / 64; i = rem % 64;
        src = g_q; dh = g_qh; dl = g_ql; stride = DMODEL;
        postscale = 0.08838834764831845f;
    } else {
        long long t = idx - QP;
        s = (int)(t / (HKV * 64));
        int rem = (int)(t % (HKV * 64));
        h = rem / 64; i = rem % 64;
        src = g_k; dh = g_kh; dl = g_kl; stride = DKV;
        postscale = 1.0f;
    }

    float invf = (float)(1.0 / pow(10000.0, (double)i / 64.0));
    float ang = (float)s * invf;
    double sd, cd;
    sincos((double)ang, &sd, &cd);
    float c = (float)cd, sn = (float)sd;

    size_t off = (size_t)s * (size_t)stride + (size_t)h * HD + 2 * (size_t)i;
    float x1 = src[off], x2 = src[off + 1];
    float o1 = (x1 * c - x2 * sn) * postscale;
    float o2 = (x1 * sn + x2 * c) * postscale;
    __nv_bfloat16 h1, h2, l1, l2;
    split2(o1, h1, l1); split2(o2, h2, l2);
    *(uint32_t*)(dh + off) = packpair(h1, h2);
    *(uint32_t*)(dl + off) = packpair(l1, l2);
}

// ---------------------------------------------------------------------------
// Transpose V [s][d] -> Vt [d][s], bf16 hi/lo
// ---------------------------------------------------------------------------
__global__ void transpose_v_split() {
    __shared__ float t[32][33];
    int d0 = blockIdx.x * 32;
    int s0 = blockIdx.y * 32;
    for (int i = threadIdx.y; i < 32; i += 8)
        t[i][threadIdx.x] = g_v[(size_t)(s0 + i) * DKV + d0 + threadIdx.x];
    __syncthreads();
    for (int i = threadIdx.y; i < 32; i += 8) {
        float v = t[threadIdx.x][i];
        __nv_bfloat16 h, l;
        split2(v, h, l);
        size_t o = (size_t)(d0 + i) * S_LEN + s0 + threadIdx.x;
        g_vth[o] = h;
        g_vtl[o] = l;
    }
}

// ---------------------------------------------------------------------------
// Launch
// ---------------------------------------------------------------------------
extern "C" void kernel_launch(void* const* d_in, const int* in_sizes, int n_in,
                              void* d_out, int out_size)
{
    const float* x  = (const float*)d_in[0];
    const float* wq = (const float*)d_in[1];
    const float* wk = (const float*)d_in[2];
    const float* wv = (const float*)d_in[3];
    const float* wo = (const float*)d_in[4];
    float* out = (float*)d_out;

    __nv_bfloat16 *xh, *xl, *wqh, *wql, *wkh, *wkl, *wvh, *wvl, *woh, *wol, *ah, *al;
    cudaGetSymbolAddress((void**)&xh,  g_xh);  cudaGetSymbolAddress((void**)&xl,  g_xl);
    cudaGetSymbolAddress((void**)&wqh, g_wqh); cudaGetSymbolAddress((void**)&wql, g_wql);
    cudaGetSymbolAddress((void**)&wkh, g_wkh); cudaGetSymbolAddress((void**)&wkl, g_wkl);
    cudaGetSymbolAddress((void**)&wvh, g_wvh); cudaGetSymbolAddress((void**)&wvl, g_wvl);
    cudaGetSymbolAddress((void**)&woh, g_woh); cudaGetSymbolAddress((void**)&wol, g_wol);
    cudaGetSymbolAddress((void**)&ah,  g_ah);  cudaGetSymbolAddress((void**)&al,  g_al);

    cudaFuncSetAttribute(tcg_nt,
        cudaFuncAttributeMaxDynamicSharedMemorySize, GSMEM);
    cudaFuncSetAttribute(tcg_qkv,
        cudaFuncAttributeMaxDynamicSharedMemorySize, GSMEM);
    cudaFuncSetAttribute(flash_attn2,
        cudaFuncAttributeMaxDynamicSharedMemorySize, FB_SMEM);

#define SPLIT(src, h, l, n) do {                                    \
    int n4 = (int)((n) / 4);                                        \
    int blocks = (n4 + 4 * 256 - 1) / (4 * 256);                    \
    split_f32<<<blocks, 256>>>(src, h, l, n4);                      \
} while (0)

    // 0) split inputs
    SPLIT(x,  xh,  xl,  (long long)S_LEN * DMODEL);
    SPLIT(wq, wqh, wql, (long long)DMODEL * DMODEL);
    SPLIT(wk, wkh, wkl, (long long)DKV * DMODEL);
    SPLIT(wv, wvh, wvl, (long long)DKV * DMODEL);
    SPLIT(wo, woh, wol, (long long)DMODEL * DMODEL);

    // 1) Merged Q/K/V projections
    tcg_qkv<<<dim3(48, 16), 256, GSMEM>>>();

    // 2) RoPE -> bf16 hi/lo Q (pre-scaled), K
    {
        long long total = (long long)S_LEN * HQ * 64 + (long long)S_LEN * HKV * 64;
        rope_split<<<(int)((total + 255) / 256), 256>>>();
    }

    // 3) V transpose -> bf16 hi/lo Vt
    transpose_v_split<<<dim3(DKV / 32, S_LEN / 32), dim3(32, 8)>>>();

    // 4) Fused attention v2 -> g_ah/g_al
    flash_attn2<<<dim3(S_LEN / 128, HQ), 256, FB_SMEM>>>();

    // 5) out = attn * wo^T
    tcg_nt<<<dim3(DMODEL / 128, S_LEN / 128), 256, GSMEM>>>(
        ah, al, woh, wol, out, DMODEL, DMODEL, DMODEL, DMODEL);
}

// round 13
// speedup vs baseline: 1.1268x; 1.0561x over previous
#include <cuda_runtime.h>
#include <cuda_bf16.h>
#include <cstdint>
#include <math.h>

// Problem constants
#define S_LEN  2048
#define DMODEL 4096
#define HQ     32
#define HKV    8
#define HD     128
#define DKV    (HKV * HD)   // 1024

// ---------------------------------------------------------------------------
// Scratch (device globals)
// ---------------------------------------------------------------------------
__device__ float g_q[(size_t)S_LEN * DMODEL];
__device__ float g_k[(size_t)S_LEN * DKV];
__device__ float g_v[(size_t)S_LEN * DKV];

__device__ __nv_bfloat16 g_xh[(size_t)S_LEN * DMODEL],  g_xl[(size_t)S_LEN * DMODEL];
__device__ __nv_bfloat16 g_wqh[(size_t)DMODEL * DMODEL], g_wql[(size_t)DMODEL * DMODEL];
__device__ __nv_bfloat16 g_wkh[(size_t)DKV * DMODEL],    g_wkl[(size_t)DKV * DMODEL];
__device__ __nv_bfloat16 g_wvh[(size_t)DKV * DMODEL],    g_wvl[(size_t)DKV * DMODEL];
__device__ __nv_bfloat16 g_woh[(size_t)DMODEL * DMODEL], g_wol[(size_t)DMODEL * DMODEL];
__device__ __nv_bfloat16 g_qh[(size_t)S_LEN * DMODEL],   g_ql[(size_t)S_LEN * DMODEL];
__device__ __nv_bfloat16 g_kh[(size_t)S_LEN * DKV],      g_kl[(size_t)S_LEN * DKV];
__device__ __nv_bfloat16 g_vth[(size_t)DKV * S_LEN],     g_vtl[(size_t)DKV * S_LEN];
__device__ __nv_bfloat16 g_ah[(size_t)S_LEN * DMODEL],   g_al[(size_t)S_LEN * DMODEL];

// ---------------------------------------------------------------------------
// PTX helpers
// ---------------------------------------------------------------------------
__device__ __forceinline__ uint32_t smem_u32(const void* p) {
    uint32_t a;
    asm("{ .reg .u64 t; cvta.to.shared.u64 t, %1; cvt.u32.u64 %0, t; }"
        : "=r"(a) : "l"(p));
    return a;
}
__device__ __forceinline__ void ldsm_x4(uint32_t r[4], uint32_t addr) {
    asm volatile("ldmatrix.sync.aligned.m8n8.x4.shared.b16 {%0,%1,%2,%3}, [%4];"
        : "=r"(r[0]), "=r"(r[1]), "=r"(r[2]), "=r"(r[3]) : "r"(addr));
}
__device__ __forceinline__ void mma_bf16(float d[4], const uint32_t a[4],
                                         const uint32_t b[2]) {
    asm volatile(
        "mma.sync.aligned.m16n8k16.row.col.f32.bf16.bf16.f32 "
        "{%0,%1,%2,%3}, {%4,%5,%6,%7}, {%8,%9}, {%0,%1,%2,%3};"
        : "+f"(d[0]), "+f"(d[1]), "+f"(d[2]), "+f"(d[3])
        : "r"(a[0]), "r"(a[1]), "r"(a[2]), "r"(a[3]), "r"(b[0]), "r"(b[1]));
}
#define CP_ASYNC16(sm_addr, gptr) \
    asm volatile("cp.async.cg.shared.global [%0], [%1], 16;" \
                 :: "r"(sm_addr), "l"(gptr) : "memory")
#define CP_COMMIT() asm volatile("cp.async.commit_group;" ::: "memory")
#define CP_WAIT0()  asm volatile("cp.async.wait_group 0;" ::: "memory")
#define CP_WAIT1()  asm volatile("cp.async.wait_group 1;" ::: "memory")

__device__ __forceinline__ void split2(float x, __nv_bfloat16& h, __nv_bfloat16& l) {
    h = __float2bfloat16(x);
    l = __float2bfloat16(x - __bfloat162float(h));
}
__device__ __forceinline__ uint32_t packpair(__nv_bfloat16 a, __nv_bfloat16 b) {
    __nv_bfloat162 t = __halves2bfloat162(a, b);
    return *reinterpret_cast<uint32_t*>(&t);
}

// ---------------------------------------------------------------------------
// GEMM core v2: 128 threads (4 warps), warp tile 64x64, CTA tile 128x128,
// K-step 32, cp.async double-buffer. C = (Ah+Al)(Bh+Bl)^T.
// ---------------------------------------------------------------------------
#define TILE_B (128 * 80)
#define STAGE_B (4 * TILE_B)
#define GSMEM  (2 * STAGE_B)

__device__ __forceinline__ void gemm_core(
    const __nv_bfloat16* __restrict__ Ah, const __nv_bfloat16* __restrict__ Al,
    const __nv_bfloat16* __restrict__ Bh, const __nv_bfloat16* __restrict__ Bl,
    float* __restrict__ C, int K, int lda, int ldb, int ldc,
    int row0, int col0, char* smem)
{
    const uint32_t sbase = smem_u32(smem);
    const int tid  = threadIdx.x;        // 0..127
    const int lane = tid & 31;
    const int w    = tid >> 5;           // 0..3
    const int wm   = (w & 1) * 64;
    const int wn   = (w >> 1) * 64;

    float acc[4][8][4];
#pragma unroll
    for (int i = 0; i < 4; i++)
#pragma unroll
        for (int j = 0; j < 8; j++)
#pragma unroll
            for (int e = 0; e < 4; e++) acc[i][j][e] = 0.f;

    const int KT = K / 32;

// per tile: 128 rows x 4 chunks of 16B = 512 chunks over 128 threads -> 4 each
#define PREFETCH(kt, stage) do {                                               \
    const int k0 = (kt) * 32;                                                  \
    const uint32_t ss = sbase + (stage) * STAGE_B;                             \
    _Pragma("unroll")                                                          \
    for (int u_ = 0; u_ < 4; u_++) {                                           \
        int idx_ = tid + 128 * u_;                                             \
        int r_   = idx_ >> 2;                                                  \
        int ck_  = idx_ & 3;                                                   \
        uint32_t so_ = (uint32_t)(r_ * 80 + ck_ * 16);                         \
        const __nv_bfloat16* pa = Ah + (long long)(row0 + r_) * lda + k0 + ck_ * 8; \
        const __nv_bfloat16* pal = Al + (long long)(row0 + r_) * lda + k0 + ck_ * 8;\
        const __nv_bfloat16* pb = Bh + (long long)(col0 + r_) * ldb + k0 + ck_ * 8; \
        const __nv_bfloat16* pbl = Bl + (long long)(col0 + r_) * ldb + k0 + ck_ * 8;\
        CP_ASYNC16(ss + so_, pa);                                              \
        CP_ASYNC16(ss + TILE_B + so_, pal);                                    \
        CP_ASYNC16(ss + 2 * TILE_B + so_, pb);                                 \
        CP_ASYNC16(ss + 3 * TILE_B + so_, pbl);                                \
    }                                                                          \
} while (0)

    PREFETCH(0, 0);
    CP_COMMIT();

    for (int kt = 0; kt < KT; kt++) {
        CP_WAIT0();
        __syncthreads();
        if (kt + 1 < KT) {
            PREFETCH(kt + 1, (kt + 1) & 1);
            CP_COMMIT();
        }
        const uint32_t ss = sbase + (kt & 1) * STAGE_B;
        const uint32_t ah0 = ss, al0 = ss + TILE_B;
        const uint32_t bh0 = ss + 2 * TILE_B, bl0 = ss + 3 * TILE_B;

#pragma unroll
        for (int kc = 0; kc < 2; kc++) {
            const int kb = kc * 16;
            uint32_t afh[4][4], afl[4][4];
            {
                int rr = lane & 15;
                int cc = kb + ((lane >> 4) << 3);
#pragma unroll
                for (int mi = 0; mi < 4; mi++) {
                    uint32_t off = (uint32_t)((wm + mi * 16 + rr) * 80 + cc * 2);
                    ldsm_x4(afh[mi], ah0 + off);
                    ldsm_x4(afl[mi], al0 + off);
                }
            }
            {
                int rr    = lane & 7;
                int cc    = kb + (((lane >> 3) & 1) << 3);
                int njoff = (lane >> 4) << 3;
#pragma unroll
                for (int njp = 0; njp < 4; njp++) {
                    uint32_t bh4[4], bl4[4];
                    uint32_t off = (uint32_t)((wn + njp * 16 + njoff + rr) * 80 + cc * 2);
                    ldsm_x4(bh4, bh0 + off);
                    ldsm_x4(bl4, bl0 + off);
#pragma unroll
                    for (int mi = 0; mi < 4; mi++) {
                        mma_bf16(acc[mi][2 * njp], afh[mi], bh4);
                        mma_bf16(acc[mi][2 * njp], afh[mi], bl4);
                        mma_bf16(acc[mi][2 * njp], afl[mi], bh4);
                        mma_bf16(acc[mi][2 * njp + 1], afh[mi], bh4 + 2);
                        mma_bf16(acc[mi][2 * njp + 1], afh[mi], bl4 + 2);
                        mma_bf16(acc[mi][2 * njp + 1], afl[mi], bh4 + 2);
                    }
                }
            }
        }
        __syncthreads();
    }
#undef PREFETCH

#pragma unroll
    for (int mi = 0; mi < 4; mi++)
#pragma unroll
        for (int nj = 0; nj < 8; nj++) {
            int r = row0 + wm + mi * 16 + (lane >> 2);
            int c = col0 + wn + nj * 8 + (lane & 3) * 2;
            float* p0 = C + (long long)r * ldc + c;
            p0[0] = acc[mi][nj][0];
            p0[1] = acc[mi][nj][1];
            float* p1 = C + (long long)(r + 8) * ldc + c;
            p1[0] = acc[mi][nj][2];
            p1[1] = acc[mi][nj][3];
        }
}

// Merged Q/K/V projection: grid (48, 16), 128 threads
__global__ __launch_bounds__(128) void tcg_qkv() {
    extern __shared__ char smem[];
    const int cb = blockIdx.x;
    const __nv_bfloat16 *Bh, *Bl; float* C; int ldc, col0;
    if (cb < 32)      { Bh = g_wqh; Bl = g_wql; C = g_q; ldc = DMODEL; col0 = cb * 128; }
    else if (cb < 40) { Bh = g_wkh; Bl = g_wkl; C = g_k; ldc = DKV;    col0 = (cb - 32) * 128; }
    else              { Bh = g_wvh; Bl = g_wvl; C = g_v; ldc = DKV;    col0 = (cb - 40) * 128; }
    gemm_core(g_xh, g_xl, Bh, Bl, C, DMODEL, DMODEL, DMODEL, ldc,
              blockIdx.y * 128, col0, smem);
}

// Generic NT GEMM (wo), 128 threads
__global__ __launch_bounds__(128) void tcg_nt(
    const __nv_bfloat16* __restrict__ Ah, const __nv_bfloat16* __restrict__ Al,
    const __nv_bfloat16* __restrict__ Bh, const __nv_bfloat16* __restrict__ Bl,
    float* __restrict__ C, int K, int lda, int ldb, int ldc)
{
    extern __shared__ char smem[];
    gemm_core(Ah, Al, Bh, Bl, C, K, lda, ldb, ldc,
              blockIdx.y * 128, blockIdx.x * 128, smem);
}

// ---------------------------------------------------------------------------
// Flash attention v2 (unchanged R11 winner): q-tile 128, k-tile 64,
// 256 threads, double-buffered K/V stages.
// ---------------------------------------------------------------------------
#define FB_QH 0
#define FB_QL 34816
#define FB_K(st) (69632 + (st) * 34816)
#define FB_V(st) (139264 + (st) * 36864)
#define FB_SMEM 212992

__global__ __launch_bounds__(256) void flash_attn2() {
    extern __shared__ char smem[];
    const uint32_t sb = smem_u32(smem);

    const int qb   = blockIdx.x;
    const int h    = blockIdx.y;
    const int kvh  = h >> 2;
    const int q0   = qb * 128;
    const int tid  = threadIdx.x;
    const int lane = tid & 31;
    const int w    = tid >> 5;

#pragma unroll
    for (int i = 0; i < 8; i++) {
        int idx = tid + 256 * i;
        int r = idx >> 4;
        int ck = idx & 15;
        uint32_t so = (uint32_t)(r * 272 + ck * 16);
        CP_ASYNC16(sb + FB_QH + so, g_qh + (long long)(q0 + r) * DMODEL + h * HD + ck * 8);
        CP_ASYNC16(sb + FB_QL + so, g_ql + (long long)(q0 + r) * DMODEL + h * HD + ck * 8);
    }
    CP_COMMIT();

#define FB_PREFETCH(kt, st) do {                                              \
    const int s0_ = (kt) * 64;                                                \
    const uint32_t kb_ = sb + FB_K(st);                                       \
    const uint32_t vb_ = sb + FB_V(st);                                       \
    _Pragma("unroll")                                                         \
    for (int i_ = 0; i_ < 4; i_++) {                                          \
        int idx_ = tid + 256 * i_;                                            \
        int r_ = idx_ >> 4;                                                   \
        int ck_ = idx_ & 15;                                                  \
        uint32_t so_ = (uint32_t)(r_ * 272 + ck_ * 16);                       \
        CP_ASYNC16(kb_ + so_,         g_kh + (long long)(s0_ + r_) * DKV + kvh * HD + ck_ * 8); \
        CP_ASYNC16(kb_ + 17408 + so_, g_kl + (long long)(s0_ + r_) * DKV + kvh * HD + ck_ * 8); \
    }                                                                         \
    _Pragma("unroll")                                                         \
    for (int i_ = 0; i_ < 4; i_++) {                                          \
        int idx_ = tid + 256 * i_;                                            \
        int r_ = idx_ >> 3;                                                   \
        int ck_ = idx_ & 7;                                                   \
        uint32_t so_ = (uint32_t)(r_ * 144 + ck_ * 16);                       \
        CP_ASYNC16(vb_ + so_,         g_vth + (long long)(kvh * HD + r_) * S_LEN + s0_ + ck_ * 8); \
        CP_ASYNC16(vb_ + 18432 + so_, g_vtl + (long long)(kvh * HD + r_) * S_LEN + s0_ + ck_ * 8); \
    }                                                                         \
} while (0)

    FB_PREFETCH(0, 0);
    CP_COMMIT();

    float out[16][4];
#pragma unroll
    for (int i = 0; i < 16; i++)
#pragma unroll
        for (int e = 0; e < 4; e++) out[i][e] = 0.f;
    float m0 = -1e30f, m1 = -1e30f, l0 = 0.f, l1 = 0.f;

    for (int kt = 0; kt < S_LEN / 64; kt++) {
        if (kt + 1 < S_LEN / 64) {
            FB_PREFETCH(kt + 1, (kt + 1) & 1);
            CP_COMMIT();
            CP_WAIT1();
        } else {
            CP_WAIT0();
        }
        __syncthreads();

        const uint32_t kh0 = sb + FB_K(kt & 1);
        const uint32_t kl0 = kh0 + 17408;
        const uint32_t vh0 = sb + FB_V(kt & 1);
        const uint32_t vl0 = vh0 + 18432;

        float s_acc[8][4];
#pragma unroll
        for (int nj = 0; nj < 8; nj++)
#pragma unroll
            for (int e = 0; e < 4; e++) s_acc[nj][e] = 0.f;

#pragma unroll
        for (int kc = 0; kc < 8; kc++) {
            uint32_t qa_h[4], qa_l[4];
            {
                int rr = lane & 15;
                int cc = kc * 16 + ((lane >> 4) << 3);
                uint32_t off = (uint32_t)((w * 16 + rr) * 272 + cc * 2);
                ldsm_x4(qa_h, sb + FB_QH + off);
                ldsm_x4(qa_l, sb + FB_QL + off);
            }
            int rr    = lane & 7;
            int cc    = kc * 16 + (((lane >> 3) & 1) << 3);
            int njoff = (lane >> 4) << 3;
#pragma unroll
            for (int njp = 0; njp < 4; njp++) {
                uint32_t bh4[4], bl4[4];
                uint32_t off = (uint32_t)((njp * 16 + njoff + rr) * 272 + cc * 2);
                ldsm_x4(bh4, kh0 + off);
                ldsm_x4(bl4, kl0 + off);
                mma_bf16(s_acc[2 * njp], qa_h, bh4);
                mma_bf16(s_acc[2 * njp], qa_h, bl4);
                mma_bf16(s_acc[2 * njp], qa_l, bh4);
                mma_bf16(s_acc[2 * njp + 1], qa_h, bh4 + 2);
                mma_bf16(s_acc[2 * njp + 1], qa_h, bl4 + 2);
                mma_bf16(s_acc[2 * njp + 1], qa_l, bh4 + 2);
            }
        }

        float mt0 = -1e30f, mt1 = -1e30f;
#pragma unroll
        for (int nj = 0; nj < 8; nj++) {
            mt0 = fmaxf(mt0, fmaxf(s_acc[nj][0], s_acc[nj][1]));
            mt1 = fmaxf(mt1, fmaxf(s_acc[nj][2], s_acc[nj][3]));
        }
        mt0 = fmaxf(mt0, __shfl_xor_sync(0xffffffffu, mt0, 1));
        mt0 = fmaxf(mt0, __shfl_xor_sync(0xffffffffu, mt0, 2));
        mt1 = fmaxf(mt1, __shfl_xor_sync(0xffffffffu, mt1, 1));
        mt1 = fmaxf(mt1, __shfl_xor_sync(0xffffffffu, mt1, 2));

        float mn0 = fmaxf(m0, mt0), mn1 = fmaxf(m1, mt1);
        float a0 = __expf(m0 - mn0), a1 = __expf(m1 - mn1);
        float sum0 = 0.f, sum1 = 0.f;
#pragma unroll
        for (int nj = 0; nj < 8; nj++) {
            s_acc[nj][0] = __expf(s_acc[nj][0] - mn0);
            s_acc[nj][1] = __expf(s_acc[nj][1] - mn0);
            s_acc[nj][2] = __expf(s_acc[nj][2] - mn1);
            s_acc[nj][3] = __expf(s_acc[nj][3] - mn1);
            sum0 += s_acc[nj][0] + s_acc[nj][1];
            sum1 += s_acc[nj][2] + s_acc[nj][3];
        }
        sum0 += __shfl_xor_sync(0xffffffffu, sum0, 1);
        sum0 += __shfl_xor_sync(0xffffffffu, sum0, 2);
        sum1 += __shfl_xor_sync(0xffffffffu, sum1, 1);
        sum1 += __shfl_xor_sync(0xffffffffu, sum1, 2);
        l0 = l0 * a0 + sum0;  m0 = mn0;
        l1 = l1 * a1 + sum1;  m1 = mn1;
#pragma unroll
        for (int i = 0; i < 16; i++) {
            out[i][0] *= a0; out[i][1] *= a0;
            out[i][2] *= a1; out[i][3] *= a1;
        }

#pragma unroll
        for (int kc = 0; kc < 4; kc++) {
            uint32_t pah[4], pal[4];
            {
                __nv_bfloat16 h0, h1, lo0, lo1;
                split2(s_acc[2 * kc][0], h0, lo0); split2(s_acc[2 * kc][1], h1, lo1);
                pah[0] = packpair(h0, h1); pal[0] = packpair(lo0, lo1);
                split2(s_acc[2 * kc][2], h0, lo0); split2(s_acc[2 * kc][3], h1, lo1);
                pah[1] = packpair(h0, h1); pal[1] = packpair(lo0, lo1);
                split2(s_acc[2 * kc + 1][0], h0, lo0); split2(s_acc[2 * kc + 1][1], h1, lo1);
                pah[2] = packpair(h0, h1); pal[2] = packpair(lo0, lo1);
                split2(s_acc[2 * kc + 1][2], h0, lo0); split2(s_acc[2 * kc + 1][3], h1, lo1);
                pah[3] = packpair(h0, h1); pal[3] = packpair(lo0, lo1);
            }
            int rr    = lane & 7;
            int cc    = kc * 16 + (((lane >> 3) & 1) << 3);
            int ndoff = (lane >> 4) << 3;
#pragma unroll
            for (int ndp = 0; ndp < 8; ndp++) {
                uint32_t vh4[4], vl4[4];
                uint32_t off = (uint32_t)((ndp * 16 + ndoff + rr) * 144 + cc * 2);
                ldsm_x4(vh4, vh0 + off);
                ldsm_x4(vl4, vl0 + off);
                mma_bf16(out[2 * ndp], pah, vh4);
                mma_bf16(out[2 * ndp], pah, vl4);
                mma_bf16(out[2 * ndp], pal, vh4);
                mma_bf16(out[2 * ndp + 1], pah, vh4 + 2);
                mma_bf16(out[2 * ndp + 1], pah, vl4 + 2);
                mma_bf16(out[2 * ndp + 1], pal, vh4 + 2);
            }
        }
        __syncthreads();
    }

    float inv0 = 1.0f / l0, inv1 = 1.0f / l1;
    int row0 = q0 + w * 16 + (lane >> 2);
    int row1 = row0 + 8;
#pragma unroll
    for (int nd = 0; nd < 16; nd++) {
        int col = h * HD + nd * 8 + (lane & 3) * 2;
        __nv_bfloat16 h0, h1, lo0, lo1;
        split2(out[nd][0] * inv0, h0, lo0);
        split2(out[nd][1] * inv0, h1, lo1);
        *(uint32_t*)(g_ah + (size_t)row0 * DMODEL + col) = packpair(h0, h1);
        *(uint32_t*)(g_al + (size_t)row0 * DMODEL + col) = packpair(lo0, lo1);
        split2(out[nd][2] * inv1, h0, lo0);
        split2(out[nd][3] * inv1, h1, lo1);
        *(uint32_t*)(g_ah + (size_t)row1 * DMODEL + col) = packpair(h0, h1);
        *(uint32_t*)(g_al + (size_t)row1 * DMODEL + col) = packpair(lo0, lo1);
    }
}

// ---------------------------------------------------------------------------
// Split: fp32 -> bf16 hi/lo, MLP=4 grid-stride
// ---------------------------------------------------------------------------
__global__ void split_f32(const float* __restrict__ in,
                          __nv_bfloat16* __restrict__ hi,
                          __nv_bfloat16* __restrict__ lo, int n4)
{
    const int stride = gridDim.x * blockDim.x;
    const int i0 = blockIdx.x * blockDim.x + threadIdx.x;
    float4 v[4]; int idx[4]; int cnt = 0;
#pragma unroll
    for (int u = 0; u < 4; u++) {
        int j = i0 + u * stride;
        if (j < n4) { idx[cnt] = j; v[cnt] = ((const float4*)in)[j]; cnt++; }
    }
#pragma unroll 4
    for (int t = 0; t < cnt; t++) {
        __nv_bfloat16 h0, h1, h2, h3, l0, l1, l2, l3;
        split2(v[t].x, h0, l0); split2(v[t].y, h1, l1);
        split2(v[t].z, h2, l2); split2(v[t].w, h3, l3);
        ((uint2*)hi)[idx[t]] = make_uint2(packpair(h0, h1), packpair(h2, h3));
        ((uint2*)lo)[idx[t]] = make_uint2(packpair(l0, l1), packpair(l2, l3));
    }
}

// ---------------------------------------------------------------------------
// RoPE: fp32 in, bf16 hi/lo out; Q pre-scaled by 1/sqrt(128)
// ---------------------------------------------------------------------------
__global__ void rope_split() {
    long long idx = (long long)blockIdx.x * blockDim.x + threadIdx.x;
    const long long QP = (long long)S_LEN * HQ * 64;
    const long long KP = (long long)S_LEN * HKV * 64;
    if (idx >= QP + KP) return;

    const float* src; __nv_bfloat16 *dh, *dl;
    int s, h, i, stride; float postscale;
    if (idx < QP) {
        s = (int)(idx / (HQ * 64));
        int rem = (int)(idx % (HQ * 64));
        h = rem / 64; i = rem % 64;
        src = g_q; dh = g_qh; dl = g_ql; stride = DMODEL;
        postscale = 0.08838834764831845f;
    } else {
        long long t = idx - QP;
        s = (int)(t / (HKV * 64));
        int rem = (int)(t % (HKV * 64));
        h = rem / 64; i = rem % 64;
        src = g_k; dh = g_kh; dl = g_kl; stride = DKV;
        postscale = 1.0f;
    }

    float invf = (float)(1.0 / pow(10000.0, (double)i / 64.0));
    float ang = (float)s * invf;
    double sd, cd;
    sincos((double)ang, &sd, &cd);
    float c = (float)cd, sn = (float)sd;

    size_t off = (size_t)s * (size_t)stride + (size_t)h * HD + 2 * (size_t)i;
    float x1 = src[off], x2 = src[off + 1];
    float o1 = (x1 * c - x2 * sn) * postscale;
    float o2 = (x1 * sn + x2 * c) * postscale;
    __nv_bfloat16 h1, h2, l1, l2;
    split2(o1, h1, l1); split2(o2, h2, l2);
    *(uint32_t*)(dh + off) = packpair(h1, h2);
    *(uint32_t*)(dl + off) = packpair(l1, l2);
}

// ---------------------------------------------------------------------------
// Transpose V [s][d] -> Vt [d][s], bf16 hi/lo
// ---------------------------------------------------------------------------
__global__ void transpose_v_split() {
    __shared__ float t[32][33];
    int d0 = blockIdx.x * 32;
    int s0 = blockIdx.y * 32;
    for (int i = threadIdx.y; i < 32; i += 8)
        t[i][threadIdx.x] = g_v[(size_t)(s0 + i) * DKV + d0 + threadIdx.x];
    __syncthreads();
    for (int i = threadIdx.y; i < 32; i += 8) {
        float v = t[threadIdx.x][i];
        __nv_bfloat16 h, l;
        split2(v, h, l);
        size_t o = (size_t)(d0 + i) * S_LEN + s0 + threadIdx.x;
        g_vth[o] = h;
        g_vtl[o] = l;
    }
}

// ---------------------------------------------------------------------------
// Launch
// ---------------------------------------------------------------------------
extern "C" void kernel_launch(void* const* d_in, const int* in_sizes, int n_in,
                              void* d_out, int out_size)
{
    const float* x  = (const float*)d_in[0];
    const float* wq = (const float*)d_in[1];
    const float* wk = (const float*)d_in[2];
    const float* wv = (const float*)d_in[3];
    const float* wo = (const float*)d_in[4];
    float* out = (float*)d_out;

    __nv_bfloat16 *xh, *xl, *wqh, *wql, *wkh, *wkl, *wvh, *wvl, *woh, *wol, *ah, *al;
    cudaGetSymbolAddress((void**)&xh,  g_xh);  cudaGetSymbolAddress((void**)&xl,  g_xl);
    cudaGetSymbolAddress((void**)&wqh, g_wqh); cudaGetSymbolAddress((void**)&wql, g_wql);
    cudaGetSymbolAddress((void**)&wkh, g_wkh); cudaGetSymbolAddress((void**)&wkl, g_wkl);
    cudaGetSymbolAddress((void**)&wvh, g_wvh); cudaGetSymbolAddress((void**)&wvl, g_wvl);
    cudaGetSymbolAddress((void**)&woh, g_woh); cudaGetSymbolAddress((void**)&wol, g_wol);
    cudaGetSymbolAddress((void**)&ah,  g_ah);  cudaGetSymbolAddress((void**)&al,  g_al);

    cudaFuncSetAttribute(tcg_nt,
        cudaFuncAttributeMaxDynamicSharedMemorySize, GSMEM);
    cudaFuncSetAttribute(tcg_qkv,
        cudaFuncAttributeMaxDynamicSharedMemorySize, GSMEM);
    cudaFuncSetAttribute(flash_attn2,
        cudaFuncAttributeMaxDynamicSharedMemorySize, FB_SMEM);

#define SPLIT(src, h, l, n) do {                                    \
    int n4 = (int)((n) / 4);                                        \
    int blocks = (n4 + 4 * 256 - 1) / (4 * 256);                    \
    split_f32<<<blocks, 256>>>(src, h, l, n4);                      \
} while (0)

    // 0) split inputs
    SPLIT(x,  xh,  xl,  (long long)S_LEN * DMODEL);
    SPLIT(wq, wqh, wql, (long long)DMODEL * DMODEL);
    SPLIT(wk, wkh, wkl, (long long)DKV * DMODEL);
    SPLIT(wv, wvh, wvl, (long long)DKV * DMODEL);
    SPLIT(wo, woh, wol, (long long)DMODEL * DMODEL);

    // 1) Merged Q/K/V projections
    tcg_qkv<<<dim3(48, 16), 128, GSMEM>>>();

    // 2) RoPE -> bf16 hi/lo Q (pre-scaled), K
    {
        long long total = (long long)S_LEN * HQ * 64 + (long long)S_LEN * HKV * 64;
        rope_split<<<(int)((total + 255) / 256), 256>>>();
    }

    // 3) V transpose -> bf16 hi/lo Vt
    transpose_v_split<<<dim3(DKV / 32, S_LEN / 32), dim3(32, 8)>>>();

    // 4) Fused attention v2 -> g_ah/g_al
    flash_attn2<<<dim3(S_LEN / 128, HQ), 256, FB_SMEM>>>();

    // 5) out = attn * wo^T
    tcg_nt<<<dim3(DMODEL / 128, S_LEN / 128), 128, GSMEM>>>(
        ah, al, woh, wol, out, DMODEL, DMODEL, DMODEL, DMODEL);
}

// round 14
// speedup vs baseline: 1.1380x; 1.0100x over previous
#include <cuda_runtime.h>
#include <cuda_bf16.h>
#include <cstdint>
#include <math.h>

// Problem constants
#define S_LEN  2048
#define DMODEL 4096
#define HQ     32
#define HKV    8
#define HD     128
#define DKV    (HKV * HD)   // 1024

// ---------------------------------------------------------------------------
// Scratch (device globals)
// ---------------------------------------------------------------------------
__device__ float g_q[(size_t)S_LEN * DMODEL];
__device__ float g_k[(size_t)S_LEN * DKV];
__device__ float g_v[(size_t)S_LEN * DKV];

__device__ __nv_bfloat16 g_xh[(size_t)S_LEN * DMODEL],  g_xl[(size_t)S_LEN * DMODEL];
__device__ __nv_bfloat16 g_wqh[(size_t)DMODEL * DMODEL], g_wql[(size_t)DMODEL * DMODEL];
__device__ __nv_bfloat16 g_wkh[(size_t)DKV * DMODEL],    g_wkl[(size_t)DKV * DMODEL];
__device__ __nv_bfloat16 g_wvh[(size_t)DKV * DMODEL],    g_wvl[(size_t)DKV * DMODEL];
__device__ __nv_bfloat16 g_woh[(size_t)DMODEL * DMODEL], g_wol[(size_t)DMODEL * DMODEL];
__device__ __nv_bfloat16 g_qh[(size_t)S_LEN * DMODEL],   g_ql[(size_t)S_LEN * DMODEL];
__device__ __nv_bfloat16 g_kh[(size_t)S_LEN * DKV],      g_kl[(size_t)S_LEN * DKV];
__device__ __nv_bfloat16 g_vth[(size_t)DKV * S_LEN],     g_vtl[(size_t)DKV * S_LEN];
__device__ __nv_bfloat16 g_ah[(size_t)S_LEN * DMODEL],   g_al[(size_t)S_LEN * DMODEL];

// ---------------------------------------------------------------------------
// PTX helpers
// ---------------------------------------------------------------------------
__device__ __forceinline__ uint32_t smem_u32(const void* p) {
    uint32_t a;
    asm("{ .reg .u64 t; cvta.to.shared.u64 t, %1; cvt.u32.u64 %0, t; }"
        : "=r"(a) : "l"(p));
    return a;
}
__device__ __forceinline__ void ldsm_x4(uint32_t r[4], uint32_t addr) {
    asm volatile("ldmatrix.sync.aligned.m8n8.x4.shared.b16 {%0,%1,%2,%3}, [%4];"
        : "=r"(r[0]), "=r"(r[1]), "=r"(r[2]), "=r"(r[3]) : "r"(addr));
}
__device__ __forceinline__ void mma_bf16(float d[4], const uint32_t a[4],
                                         const uint32_t b[2]) {
    asm volatile(
        "mma.sync.aligned.m16n8k16.row.col.f32.bf16.bf16.f32 "
        "{%0,%1,%2,%3}, {%4,%5,%6,%7}, {%8,%9}, {%0,%1,%2,%3};"
        : "+f"(d[0]), "+f"(d[1]), "+f"(d[2]), "+f"(d[3])
        : "r"(a[0]), "r"(a[1]), "r"(a[2]), "r"(a[3]), "r"(b[0]), "r"(b[1]));
}
#define CP_ASYNC16(sm_addr, gptr) \
    asm volatile("cp.async.cg.shared.global [%0], [%1], 16;" \
                 :: "r"(sm_addr), "l"(gptr) : "memory")
#define CP_COMMIT() asm volatile("cp.async.commit_group;" ::: "memory")
#define CP_WAIT0()  asm volatile("cp.async.wait_group 0;" ::: "memory")
#define CP_WAIT1()  asm volatile("cp.async.wait_group 1;" ::: "memory")

__device__ __forceinline__ void split2(float x, __nv_bfloat16& h, __nv_bfloat16& l) {
    h = __float2bfloat16(x);
    l = __float2bfloat16(x - __bfloat162float(h));
}
__device__ __forceinline__ uint32_t packpair(__nv_bfloat16 a, __nv_bfloat16 b) {
    __nv_bfloat162 t = __halves2bfloat162(a, b);
    return *reinterpret_cast<uint32_t*>(&t);
}

// ---------------------------------------------------------------------------
// GEMM core v2 (R12 winner): 128 threads, warp tile 64x64, CTA tile 128x128
// ---------------------------------------------------------------------------
#define TILE_B (128 * 80)
#define STAGE_B (4 * TILE_B)
#define GSMEM  (2 * STAGE_B)

__device__ __forceinline__ void gemm_core(
    const __nv_bfloat16* __restrict__ Ah, const __nv_bfloat16* __restrict__ Al,
    const __nv_bfloat16* __restrict__ Bh, const __nv_bfloat16* __restrict__ Bl,
    float* __restrict__ C, int K, int lda, int ldb, int ldc,
    int row0, int col0, char* smem)
{
    const uint32_t sbase = smem_u32(smem);
    const int tid  = threadIdx.x;
    const int lane = tid & 31;
    const int w    = tid >> 5;
    const int wm   = (w & 1) * 64;
    const int wn   = (w >> 1) * 64;

    float acc[4][8][4];
#pragma unroll
    for (int i = 0; i < 4; i++)
#pragma unroll
        for (int j = 0; j < 8; j++)
#pragma unroll
            for (int e = 0; e < 4; e++) acc[i][j][e] = 0.f;

    const int KT = K / 32;

#define PREFETCH(kt, stage) do {                                               \
    const int k0 = (kt) * 32;                                                  \
    const uint32_t ss = sbase + (stage) * STAGE_B;                             \
    _Pragma("unroll")                                                          \
    for (int u_ = 0; u_ < 4; u_++) {                                           \
        int idx_ = tid + 128 * u_;                                             \
        int r_   = idx_ >> 2;                                                  \
        int ck_  = idx_ & 3;                                                   \
        uint32_t so_ = (uint32_t)(r_ * 80 + ck_ * 16);                         \
        CP_ASYNC16(ss + so_,              Ah + (long long)(row0 + r_) * lda + k0 + ck_ * 8); \
        CP_ASYNC16(ss + TILE_B + so_,     Al + (long long)(row0 + r_) * lda + k0 + ck_ * 8); \
        CP_ASYNC16(ss + 2 * TILE_B + so_, Bh + (long long)(col0 + r_) * ldb + k0 + ck_ * 8); \
        CP_ASYNC16(ss + 3 * TILE_B + so_, Bl + (long long)(col0 + r_) * ldb + k0 + ck_ * 8); \
    }                                                                          \
} while (0)

    PREFETCH(0, 0);
    CP_COMMIT();

    for (int kt = 0; kt < KT; kt++) {
        CP_WAIT0();
        __syncthreads();
        if (kt + 1 < KT) {
            PREFETCH(kt + 1, (kt + 1) & 1);
            CP_COMMIT();
        }
        const uint32_t ss = sbase + (kt & 1) * STAGE_B;
        const uint32_t ah0 = ss, al0 = ss + TILE_B;
        const uint32_t bh0 = ss + 2 * TILE_B, bl0 = ss + 3 * TILE_B;

#pragma unroll
        for (int kc = 0; kc < 2; kc++) {
            const int kb = kc * 16;
            uint32_t afh[4][4], afl[4][4];
            {
                int rr = lane & 15;
                int cc = kb + ((lane >> 4) << 3);
#pragma unroll
                for (int mi = 0; mi < 4; mi++) {
                    uint32_t off = (uint32_t)((wm + mi * 16 + rr) * 80 + cc * 2);
                    ldsm_x4(afh[mi], ah0 + off);
                    ldsm_x4(afl[mi], al0 + off);
                }
            }
            {
                int rr    = lane & 7;
                int cc    = kb + (((lane >> 3) & 1) << 3);
                int njoff = (lane >> 4) << 3;
#pragma unroll
                for (int njp = 0; njp < 4; njp++) {
                    uint32_t bh4[4], bl4[4];
                    uint32_t off = (uint32_t)((wn + njp * 16 + njoff + rr) * 80 + cc * 2);
                    ldsm_x4(bh4, bh0 + off);
                    ldsm_x4(bl4, bl0 + off);
#pragma unroll
                    for (int mi = 0; mi < 4; mi++) {
                        mma_bf16(acc[mi][2 * njp], afh[mi], bh4);
                        mma_bf16(acc[mi][2 * njp], afh[mi], bl4);
                        mma_bf16(acc[mi][2 * njp], afl[mi], bh4);
                        mma_bf16(acc[mi][2 * njp + 1], afh[mi], bh4 + 2);
                        mma_bf16(acc[mi][2 * njp + 1], afh[mi], bl4 + 2);
                        mma_bf16(acc[mi][2 * njp + 1], afl[mi], bh4 + 2);
                    }
                }
            }
        }
        __syncthreads();
    }
#undef PREFETCH

#pragma unroll
    for (int mi = 0; mi < 4; mi++)
#pragma unroll
        for (int nj = 0; nj < 8; nj++) {
            int r = row0 + wm + mi * 16 + (lane >> 2);
            int c = col0 + wn + nj * 8 + (lane & 3) * 2;
            float* p0 = C + (long long)r * ldc + c;
            p0[0] = acc[mi][nj][0];
            p0[1] = acc[mi][nj][1];
            float* p1 = C + (long long)(r + 8) * ldc + c;
            p1[0] = acc[mi][nj][2];
            p1[1] = acc[mi][nj][3];
        }
}

// Merged Q/K/V projection
__global__ __launch_bounds__(128) void tcg_qkv() {
    extern __shared__ char smem[];
    const int cb = blockIdx.x;
    const __nv_bfloat16 *Bh, *Bl; float* C; int ldc, col0;
    if (cb < 32)      { Bh = g_wqh; Bl = g_wql; C = g_q; ldc = DMODEL; col0 = cb * 128; }
    else if (cb < 40) { Bh = g_wkh; Bl = g_wkl; C = g_k; ldc = DKV;    col0 = (cb - 32) * 128; }
    else              { Bh = g_wvh; Bl = g_wvl; C = g_v; ldc = DKV;    col0 = (cb - 40) * 128; }
    gemm_core(g_xh, g_xl, Bh, Bl, C, DMODEL, DMODEL, DMODEL, ldc,
              blockIdx.y * 128, col0, smem);
}

// Generic NT GEMM (wo)
__global__ __launch_bounds__(128) void tcg_nt(
    const __nv_bfloat16* __restrict__ Ah, const __nv_bfloat16* __restrict__ Al,
    const __nv_bfloat16* __restrict__ Bh, const __nv_bfloat16* __restrict__ Bl,
    float* __restrict__ C, int K, int lda, int ldb, int ldc)
{
    extern __shared__ char smem[];
    gemm_core(Ah, Al, Bh, Bl, C, K, lda, ldb, ldc,
              blockIdx.y * 128, blockIdx.x * 128, smem);
}

// ---------------------------------------------------------------------------
// Flash attention v3: q-tile 128, k-tile 64, 256 threads, double-buffered K/V,
// Q fragments hoisted into registers, single __syncthreads per iteration.
// ---------------------------------------------------------------------------
#define FB_QH 0
#define FB_QL 34816
#define FB_K(st) (69632 + (st) * 34816)
#define FB_V(st) (139264 + (st) * 36864)
#define FB_SMEM 212992

__global__ __launch_bounds__(256) void flash_attn3() {
    extern __shared__ char smem[];
    const uint32_t sb = smem_u32(smem);

    const int qb   = blockIdx.x;
    const int h    = blockIdx.y;
    const int kvh  = h >> 2;
    const int q0   = qb * 128;
    const int tid  = threadIdx.x;
    const int lane = tid & 31;
    const int w    = tid >> 5;

    // ---- Q tile -> smem (group 1) ----
#pragma unroll
    for (int i = 0; i < 8; i++) {
        int idx = tid + 256 * i;
        int r = idx >> 4;
        int ck = idx & 15;
        uint32_t so = (uint32_t)(r * 272 + ck * 16);
        CP_ASYNC16(sb + FB_QH + so, g_qh + (long long)(q0 + r) * DMODEL + h * HD + ck * 8);
        CP_ASYNC16(sb + FB_QL + so, g_ql + (long long)(q0 + r) * DMODEL + h * HD + ck * 8);
    }
    CP_COMMIT();

#define FB_PREFETCH(kt, st) do {                                              \
    const int s0_ = (kt) * 64;                                                \
    const uint32_t kb_ = sb + FB_K(st);                                       \
    const uint32_t vb_ = sb + FB_V(st);                                       \
    _Pragma("unroll")                                                         \
    for (int i_ = 0; i_ < 4; i_++) {                                          \
        int idx_ = tid + 256 * i_;                                            \
        int r_ = idx_ >> 4;                                                   \
        int ck_ = idx_ & 15;                                                  \
        uint32_t so_ = (uint32_t)(r_ * 272 + ck_ * 16);                       \
        CP_ASYNC16(kb_ + so_,         g_kh + (long long)(s0_ + r_) * DKV + kvh * HD + ck_ * 8); \
        CP_ASYNC16(kb_ + 17408 + so_, g_kl + (long long)(s0_ + r_) * DKV + kvh * HD + ck_ * 8); \
    }                                                                         \
    _Pragma("unroll")                                                         \
    for (int i_ = 0; i_ < 4; i_++) {                                          \
        int idx_ = tid + 256 * i_;                                            \
        int r_ = idx_ >> 3;                                                   \
        int ck_ = idx_ & 7;                                                   \
        uint32_t so_ = (uint32_t)(r_ * 144 + ck_ * 16);                       \
        CP_ASYNC16(vb_ + so_,         g_vth + (long long)(kvh * HD + r_) * S_LEN + s0_ + ck_ * 8); \
        CP_ASYNC16(vb_ + 18432 + so_, g_vtl + (long long)(kvh * HD + r_) * S_LEN + s0_ + ck_ * 8); \
    }                                                                         \
} while (0)

    FB_PREFETCH(0, 0);      // group 2
    CP_COMMIT();

    // Wait for Q (all but newest group done), then hoist Q fragments to regs.
    CP_WAIT1();
    __syncthreads();

    uint32_t qh_r[8][4], ql_r[8][4];
    {
        int rr = lane & 15;
        int cb2 = (lane >> 4) << 3;
#pragma unroll
        for (int kc = 0; kc < 8; kc++) {
            uint32_t off = (uint32_t)((w * 16 + rr) * 272 + (kc * 16 + cb2) * 2);
            ldsm_x4(qh_r[kc], sb + FB_QH + off);
            ldsm_x4(ql_r[kc], sb + FB_QL + off);
        }
    }

    float out[16][4];
#pragma unroll
    for (int i = 0; i < 16; i++)
#pragma unroll
        for (int e = 0; e < 4; e++) out[i][e] = 0.f;
    float m0 = -1e30f, m1 = -1e30f, l0 = 0.f, l1 = 0.f;

    for (int kt = 0; kt < S_LEN / 64; kt++) {
        // single barrier: all warps done reading stage (kt+1)&1 from iter kt-1
        __syncthreads();
        if (kt + 1 < S_LEN / 64) {
            FB_PREFETCH(kt + 1, (kt + 1) & 1);
            CP_COMMIT();
            CP_WAIT1();          // stage kt complete; stage kt+1 in flight
        } else {
            CP_WAIT0();
        }

        const uint32_t kh0 = sb + FB_K(kt & 1);
        const uint32_t kl0 = kh0 + 17408;
        const uint32_t vh0 = sb + FB_V(kt & 1);
        const uint32_t vl0 = vh0 + 18432;

        // ---- QK^T ----
        float s_acc[8][4];
#pragma unroll
        for (int nj = 0; nj < 8; nj++)
#pragma unroll
            for (int e = 0; e < 4; e++) s_acc[nj][e] = 0.f;

#pragma unroll
        for (int kc = 0; kc < 8; kc++) {
            int rr    = lane & 7;
            int cc    = kc * 16 + (((lane >> 3) & 1) << 3);
            int njoff = (lane >> 4) << 3;
#pragma unroll
            for (int njp = 0; njp < 4; njp++) {
                uint32_t bh4[4], bl4[4];
                uint32_t off = (uint32_t)((njp * 16 + njoff + rr) * 272 + cc * 2);
                ldsm_x4(bh4, kh0 + off);
                ldsm_x4(bl4, kl0 + off);
                mma_bf16(s_acc[2 * njp], qh_r[kc], bh4);
                mma_bf16(s_acc[2 * njp], qh_r[kc], bl4);
                mma_bf16(s_acc[2 * njp], ql_r[kc], bh4);
                mma_bf16(s_acc[2 * njp + 1], qh_r[kc], bh4 + 2);
                mma_bf16(s_acc[2 * njp + 1], qh_r[kc], bl4 + 2);
                mma_bf16(s_acc[2 * njp + 1], ql_r[kc], bh4 + 2);
            }
        }

        // ---- online softmax ----
        float mt0 = -1e30f, mt1 = -1e30f;
#pragma unroll
        for (int nj = 0; nj < 8; nj++) {
            mt0 = fmaxf(mt0, fmaxf(s_acc[nj][0], s_acc[nj][1]));
            mt1 = fmaxf(mt1, fmaxf(s_acc[nj][2], s_acc[nj][3]));
        }
        mt0 = fmaxf(mt0, __shfl_xor_sync(0xffffffffu, mt0, 1));
        mt0 = fmaxf(mt0, __shfl_xor_sync(0xffffffffu, mt0, 2));
        mt1 = fmaxf(mt1, __shfl_xor_sync(0xffffffffu, mt1, 1));
        mt1 = fmaxf(mt1, __shfl_xor_sync(0xffffffffu, mt1, 2));

        float mn0 = fmaxf(m0, mt0), mn1 = fmaxf(m1, mt1);
        float a0 = __expf(m0 - mn0), a1 = __expf(m1 - mn1);
        float sum0 = 0.f, sum1 = 0.f;
#pragma unroll
        for (int nj = 0; nj < 8; nj++) {
            s_acc[nj][0] = __expf(s_acc[nj][0] - mn0);
            s_acc[nj][1] = __expf(s_acc[nj][1] - mn0);
            s_acc[nj][2] = __expf(s_acc[nj][2] - mn1);
            s_acc[nj][3] = __expf(s_acc[nj][3] - mn1);
            sum0 += s_acc[nj][0] + s_acc[nj][1];
            sum1 += s_acc[nj][2] + s_acc[nj][3];
        }
        sum0 += __shfl_xor_sync(0xffffffffu, sum0, 1);
        sum0 += __shfl_xor_sync(0xffffffffu, sum0, 2);
        sum1 += __shfl_xor_sync(0xffffffffu, sum1, 1);
        sum1 += __shfl_xor_sync(0xffffffffu, sum1, 2);
        l0 = l0 * a0 + sum0;  m0 = mn0;
        l1 = l1 * a1 + sum1;  m1 = mn1;
#pragma unroll
        for (int i = 0; i < 16; i++) {
            out[i][0] *= a0; out[i][1] *= a0;
            out[i][2] *= a1; out[i][3] *= a1;
        }

        // ---- PV ----
#pragma unroll
        for (int kc = 0; kc < 4; kc++) {
            uint32_t pah[4], pal[4];
            {
                __nv_bfloat16 h0, h1, lo0, lo1;
                split2(s_acc[2 * kc][0], h0, lo0); split2(s_acc[2 * kc][1], h1, lo1);
                pah[0] = packpair(h0, h1); pal[0] = packpair(lo0, lo1);
                split2(s_acc[2 * kc][2], h0, lo0); split2(s_acc[2 * kc][3], h1, lo1);
                pah[1] = packpair(h0, h1); pal[1] = packpair(lo0, lo1);
                split2(s_acc[2 * kc + 1][0], h0, lo0); split2(s_acc[2 * kc + 1][1], h1, lo1);
                pah[2] = packpair(h0, h1); pal[2] = packpair(lo0, lo1);
                split2(s_acc[2 * kc + 1][2], h0, lo0); split2(s_acc[2 * kc + 1][3], h1, lo1);
                pah[3] = packpair(h0, h1); pal[3] = packpair(lo0, lo1);
            }
            int rr    = lane & 7;
            int cc    = kc * 16 + (((lane >> 3) & 1) << 3);
            int ndoff = (lane >> 4) << 3;
#pragma unroll
            for (int ndp = 0; ndp < 8; ndp++) {
                uint32_t vh4[4], vl4[4];
                uint32_t off = (uint32_t)((ndp * 16 + ndoff + rr) * 144 + cc * 2);
                ldsm_x4(vh4, vh0 + off);
                ldsm_x4(vl4, vl0 + off);
                mma_bf16(out[2 * ndp], pah, vh4);
                mma_bf16(out[2 * ndp], pah, vl4);
                mma_bf16(out[2 * ndp], pal, vh4);
                mma_bf16(out[2 * ndp + 1], pah, vh4 + 2);
                mma_bf16(out[2 * ndp + 1], pah, vl4 + 2);
                mma_bf16(out[2 * ndp + 1], pal, vh4 + 2);
            }
        }
    }

    // ---- epilogue ----
    float inv0 = 1.0f / l0, inv1 = 1.0f / l1;
    int row0 = q0 + w * 16 + (lane >> 2);
    int row1 = row0 + 8;
#pragma unroll
    for (int nd = 0; nd < 16; nd++) {
        int col = h * HD + nd * 8 + (lane & 3) * 2;
        __nv_bfloat16 h0, h1, lo0, lo1;
        split2(out[nd][0] * inv0, h0, lo0);
        split2(out[nd][1] * inv0, h1, lo1);
        *(uint32_t*)(g_ah + (size_t)row0 * DMODEL + col) = packpair(h0, h1);
        *(uint32_t*)(g_al + (size_t)row0 * DMODEL + col) = packpair(lo0, lo1);
        split2(out[nd][2] * inv1, h0, lo0);
        split2(out[nd][3] * inv1, h1, lo1);
        *(uint32_t*)(g_ah + (size_t)row1 * DMODEL + col) = packpair(h0, h1);
        *(uint32_t*)(g_al + (size_t)row1 * DMODEL + col) = packpair(lo0, lo1);
    }
}

// ---------------------------------------------------------------------------
// Split: fp32 -> bf16 hi/lo, MLP=4 grid-stride
// ---------------------------------------------------------------------------
__global__ void split_f32(const float* __restrict__ in,
                          __nv_bfloat16* __restrict__ hi,
                          __nv_bfloat16* __restrict__ lo, int n4)
{
    const int stride = gridDim.x * blockDim.x;
    const int i0 = blockIdx.x * blockDim.x + threadIdx.x;
    float4 v[4]; int idx[4]; int cnt = 0;
#pragma unroll
    for (int u = 0; u < 4; u++) {
        int j = i0 + u * stride;
        if (j < n4) { idx[cnt] = j; v[cnt] = ((const float4*)in)[j]; cnt++; }
    }
#pragma unroll 4
    for (int t = 0; t < cnt; t++) {
        __nv_bfloat16 h0, h1, h2, h3, l0, l1, l2, l3;
        split2(v[t].x, h0, l0); split2(v[t].y, h1, l1);
        split2(v[t].z, h2, l2); split2(v[t].w, h3, l3);
        ((uint2*)hi)[idx[t]] = make_uint2(packpair(h0, h1), packpair(h2, h3));
        ((uint2*)lo)[idx[t]] = make_uint2(packpair(l0, l1), packpair(l2, l3));
    }
}

// ---------------------------------------------------------------------------
// RoPE: fp32 in, bf16 hi/lo out; Q pre-scaled by 1/sqrt(128)
// ---------------------------------------------------------------------------
__global__ void rope_split() {
    long long idx = (long long)blockIdx.x * blockDim.x + threadIdx.x;
    const long long QP = (long long)S_LEN * HQ * 64;
    const long long KP = (long long)S_LEN * HKV * 64;
    if (idx >= QP + KP) return;

    const float* src; __nv_bfloat16 *dh, *dl;
    int s, h, i, stride; float postscale;
    if (idx < QP) {
        s = (int)(idx / (HQ * 64));
        int rem = (int)(idx % (HQ * 64));
        h = rem / 64; i = rem % 64;
        src = g_q; dh = g_qh; dl = g_ql; stride = DMODEL;
        postscale = 0.08838834764831845f;
    } else {
        long long t = idx - QP;
        s = (int)(t / (HKV * 64));
        int rem = (int)(t % (HKV * 64));
        h = rem / 64; i = rem % 64;
        src = g_k; dh = g_kh; dl = g_kl; stride = DKV;
        postscale = 1.0f;
    }

    float invf = (float)(1.0 / pow(10000.0, (double)i / 64.0));
    float ang = (float)s * invf;
    double sd, cd;
    sincos((double)ang, &sd, &cd);
    float c = (float)cd, sn = (float)sd;

    size_t off = (size_t)s * (size_t)stride + (size_t)h * HD + 2 * (size_t)i;
    float x1 = src[off], x2 = src[off + 1];
    float o1 = (x1 * c - x2 * sn) * postscale;
    float o2 = (x1 * sn + x2 * c) * postscale;
    __nv_bfloat16 h1, h2, l1, l2;
    split2(o1, h1, l1); split2(o2, h2, l2);
    *(uint32_t*)(dh + off) = packpair(h1, h2);
    *(uint32_t*)(dl + off) = packpair(l1, l2);
}

// ---------------------------------------------------------------------------
// Transpose V [s][d] -> Vt [d][s], bf16 hi/lo
// ---------------------------------------------------------------------------
__global__ void transpose_v_split() {
    __shared__ float t[32][33];
    int d0 = blockIdx.x * 32;
    int s0 = blockIdx.y * 32;
    for (int i = threadIdx.y; i < 32; i += 8)
        t[i][threadIdx.x] = g_v[(size_t)(s0 + i) * DKV + d0 + threadIdx.x];
    __syncthreads();
    for (int i = threadIdx.y; i < 32; i += 8) {
        float v = t[threadIdx.x][i];
        __nv_bfloat16 h, l;
        split2(v, h, l);
        size_t o = (size_t)(d0 + i) * S_LEN + s0 + threadIdx.x;
        g_vth[o] = h;
        g_vtl[o] = l;
    }
}

// ---------------------------------------------------------------------------
// Launch
// ---------------------------------------------------------------------------
extern "C" void kernel_launch(void* const* d_in, const int* in_sizes, int n_in,
                              void* d_out, int out_size)
{
    const float* x  = (const float*)d_in[0];
    const float* wq = (const float*)d_in[1];
    const float* wk = (const float*)d_in[2];
    const float* wv = (const float*)d_in[3];
    const float* wo = (const float*)d_in[4];
    float* out = (float*)d_out;

    __nv_bfloat16 *xh, *xl, *wqh, *wql, *wkh, *wkl, *wvh, *wvl, *woh, *wol, *ah, *al;
    cudaGetSymbolAddress((void**)&xh,  g_xh);  cudaGetSymbolAddress((void**)&xl,  g_xl);
    cudaGetSymbolAddress((void**)&wqh, g_wqh); cudaGetSymbolAddress((void**)&wql, g_wql);
    cudaGetSymbolAddress((void**)&wkh, g_wkh); cudaGetSymbolAddress((void**)&wkl, g_wkl);
    cudaGetSymbolAddress((void**)&wvh, g_wvh); cudaGetSymbolAddress((void**)&wvl, g_wvl);
    cudaGetSymbolAddress((void**)&woh, g_woh); cudaGetSymbolAddress((void**)&wol, g_wol);
    cudaGetSymbolAddress((void**)&ah,  g_ah);  cudaGetSymbolAddress((void**)&al,  g_al);

    cudaFuncSetAttribute(tcg_nt,
        cudaFuncAttributeMaxDynamicSharedMemorySize, GSMEM);
    cudaFuncSetAttribute(tcg_qkv,
        cudaFuncAttributeMaxDynamicSharedMemorySize, GSMEM);
    cudaFuncSetAttribute(flash_attn3,
        cudaFuncAttributeMaxDynamicSharedMemorySize, FB_SMEM);

#define SPLIT(src, h, l, n) do {                                    \
    int n4 = (int)((n) / 4);                                        \
    int blocks = (n4 + 4 * 256 - 1) / (4 * 256);                    \
    split_f32<<<blocks, 256>>>(src, h, l, n4);                      \
} while (0)

    // 0) split inputs
    SPLIT(x,  xh,  xl,  (long long)S_LEN * DMODEL);
    SPLIT(wq, wqh, wql, (long long)DMODEL * DMODEL);
    SPLIT(wk, wkh, wkl, (long long)DKV * DMODEL);
    SPLIT(wv, wvh, wvl, (long long)DKV * DMODEL);
    SPLIT(wo, woh, wol, (long long)DMODEL * DMODEL);

    // 1) Merged Q/K/V projections
    tcg_qkv<<<dim3(48, 16), 128, GSMEM>>>();

    // 2) RoPE -> bf16 hi/lo Q (pre-scaled), K
    {
        long long total = (long long)S_LEN * HQ * 64 + (long long)S_LEN * HKV * 64;
        rope_split<<<(int)((total + 255) / 256), 256>>>();
    }

    // 3) V transpose -> bf16 hi/lo Vt
    transpose_v_split<<<dim3(DKV / 32, S_LEN / 32), dim3(32, 8)>>>();

    // 4) Fused attention v3 -> g_ah/g_al
    flash_attn3<<<dim3(S_LEN / 128, HQ), 256, FB_SMEM>>>();

    // 5) out = attn * wo^T
    tcg_nt<<<dim3(DMODEL / 128, S_LEN / 128), 128, GSMEM>>>(
        ah, al, woh, wol, out, DMODEL, DMODEL, DMODEL, DMODEL);
}

// round 17
// speedup vs baseline: 1.1569x; 1.0166x over previous
#include <cuda_runtime.h>
#include <cuda_bf16.h>
#include <cstdint>
#include <math.h>

// Problem constants
#define S_LEN  2048
#define DMODEL 4096
#define HQ     32
#define HKV    8
#define HD     128
#define DKV    (HKV * HD)   // 1024

// ---------------------------------------------------------------------------
// Scratch (device globals)
// ---------------------------------------------------------------------------
__device__ float g_q[(size_t)S_LEN * DMODEL];
__device__ float g_k[(size_t)S_LEN * DKV];
__device__ float g_v[(size_t)S_LEN * DKV];
__device__ float g_cost[(size_t)S_LEN * 64];
__device__ float g_sint[(size_t)S_LEN * 64];

__device__ __nv_bfloat16 g_xh[(size_t)S_LEN * DMODEL],  g_xl[(size_t)S_LEN * DMODEL];
__device__ __nv_bfloat16 g_wqh[(size_t)DMODEL * DMODEL], g_wql[(size_t)DMODEL * DMODEL];
__device__ __nv_bfloat16 g_wkh[(size_t)DKV * DMODEL],    g_wkl[(size_t)DKV * DMODEL];
__device__ __nv_bfloat16 g_wvh[(size_t)DKV * DMODEL],    g_wvl[(size_t)DKV * DMODEL];
__device__ __nv_bfloat16 g_woh[(size_t)DMODEL * DMODEL], g_wol[(size_t)DMODEL * DMODEL];
__device__ __nv_bfloat16 g_qh[(size_t)S_LEN * DMODEL],   g_ql[(size_t)S_LEN * DMODEL];
__device__ __nv_bfloat16 g_kh[(size_t)S_LEN * DKV],      g_kl[(size_t)S_LEN * DKV];
__device__ __nv_bfloat16 g_vth[(size_t)DKV * S_LEN],     g_vtl[(size_t)DKV * S_LEN];
__device__ __nv_bfloat16 g_ah[(size_t)S_LEN * DMODEL],   g_al[(size_t)S_LEN * DMODEL];

// ---------------------------------------------------------------------------
// PTX helpers
// ---------------------------------------------------------------------------
__device__ __forceinline__ uint32_t smem_u32(const void* p) {
    uint32_t a;
    asm("{ .reg .u64 t; cvta.to.shared.u64 t, %1; cvt.u32.u64 %0, t; }"
        : "=r"(a) : "l"(p));
    return a;
}
__device__ __forceinline__ void ldsm_x4(uint32_t r[4], uint32_t addr) {
    asm volatile("ldmatrix.sync.aligned.m8n8.x4.shared.b16 {%0,%1,%2,%3}, [%4];"
        : "=r"(r[0]), "=r"(r[1]), "=r"(r[2]), "=r"(r[3]) : "r"(addr));
}
__device__ __forceinline__ void mma_bf16(float d[4], const uint32_t a[4],
                                         const uint32_t b[2]) {
    asm volatile(
        "mma.sync.aligned.m16n8k16.row.col.f32.bf16.bf16.f32 "
        "{%0,%1,%2,%3}, {%4,%5,%6,%7}, {%8,%9}, {%0,%1,%2,%3};"
        : "+f"(d[0]), "+f"(d[1]), "+f"(d[2]), "+f"(d[3])
        : "r"(a[0]), "r"(a[1]), "r"(a[2]), "r"(a[3]), "r"(b[0]), "r"(b[1]));
}
#define CP_ASYNC16(sm_addr, gptr) \
    asm volatile("cp.async.cg.shared.global [%0], [%1], 16;" \
                 :: "r"(sm_addr), "l"(gptr) : "memory")
#define CP_COMMIT() asm volatile("cp.async.commit_group;" ::: "memory")
#define CP_WAIT0()  asm volatile("cp.async.wait_group 0;" ::: "memory")
#define CP_WAIT1()  asm volatile("cp.async.wait_group 1;" ::: "memory")

__device__ __forceinline__ void split2(float x, __nv_bfloat16& h, __nv_bfloat16& l) {
    h = __float2bfloat16(x);
    l = __float2bfloat16(x - __bfloat162float(h));
}
__device__ __forceinline__ uint32_t packpair(__nv_bfloat16 a, __nv_bfloat16 b) {
    __nv_bfloat162 t = __halves2bfloat162(a, b);
    return *reinterpret_cast<uint32_t*>(&t);
}

// ---------------------------------------------------------------------------
// GEMM core (R12/R13 winner): 128 threads, warp tile 64x64, CTA tile 128x128
// ---------------------------------------------------------------------------
#define TILE_B (128 * 80)
#define STAGE_B (4 * TILE_B)
#define GSMEM  (2 * STAGE_B)

__device__ __forceinline__ void gemm_core(
    const __nv_bfloat16* __restrict__ Ah, const __nv_bfloat16* __restrict__ Al,
    const __nv_bfloat16* __restrict__ Bh, const __nv_bfloat16* __restrict__ Bl,
    float* __restrict__ C, int K, int lda, int ldb, int ldc,
    int row0, int col0, char* smem)
{
    const uint32_t sbase = smem_u32(smem);
    const int tid  = threadIdx.x;
    const int lane = tid & 31;
    const int w    = tid >> 5;
    const int wm   = (w & 1) * 64;
    const int wn   = (w >> 1) * 64;

    float acc[4][8][4];
#pragma unroll
    for (int i = 0; i < 4; i++)
#pragma unroll
        for (int j = 0; j < 8; j++)
#pragma unroll
            for (int e = 0; e < 4; e++) acc[i][j][e] = 0.f;

    const int KT = K / 32;

#define PREFETCH(kt, stage) do {                                               \
    const int k0 = (kt) * 32;                                                  \
    const uint32_t ss = sbase + (stage) * STAGE_B;                             \
    _Pragma("unroll")                                                          \
    for (int u_ = 0; u_ < 4; u_++) {                                           \
        int idx_ = tid + 128 * u_;                                             \
        int r_   = idx_ >> 2;                                                  \
        int ck_  = idx_ & 3;                                                   \
        uint32_t so_ = (uint32_t)(r_ * 80 + ck_ * 16);                         \
        CP_ASYNC16(ss + so_,              Ah + (long long)(row0 + r_) * lda + k0 + ck_ * 8); \
        CP_ASYNC16(ss + TILE_B + so_,     Al + (long long)(row0 + r_) * lda + k0 + ck_ * 8); \
        CP_ASYNC16(ss + 2 * TILE_B + so_, Bh + (long long)(col0 + r_) * ldb + k0 + ck_ * 8); \
        CP_ASYNC16(ss + 3 * TILE_B + so_, Bl + (long long)(col0 + r_) * ldb + k0 + ck_ * 8); \
    }                                                                          \
} while (0)

    PREFETCH(0, 0);
    CP_COMMIT();

    for (int kt = 0; kt < KT; kt++) {
        CP_WAIT0();
        __syncthreads();
        if (kt + 1 < KT) {
            PREFETCH(kt + 1, (kt + 1) & 1);
            CP_COMMIT();
        }
        const uint32_t ss = sbase + (kt & 1) * STAGE_B;
        const uint32_t ah0 = ss, al0 = ss + TILE_B;
        const uint32_t bh0 = ss + 2 * TILE_B, bl0 = ss + 3 * TILE_B;

#pragma unroll
        for (int kc = 0; kc < 2; kc++) {
            const int kb = kc * 16;
            uint32_t afh[4][4], afl[4][4];
            {
                int rr = lane & 15;
                int cc = kb + ((lane >> 4) << 3);
#pragma unroll
                for (int mi = 0; mi < 4; mi++) {
                    uint32_t off = (uint32_t)((wm + mi * 16 + rr) * 80 + cc * 2);
                    ldsm_x4(afh[mi], ah0 + off);
                    ldsm_x4(afl[mi], al0 + off);
                }
            }
            {
                int rr    = lane & 7;
                int cc    = kb + (((lane >> 3) & 1) << 3);
                int njoff = (lane >> 4) << 3;
#pragma unroll
                for (int njp = 0; njp < 4; njp++) {
                    uint32_t bh4[4], bl4[4];
                    uint32_t off = (uint32_t)((wn + njp * 16 + njoff + rr) * 80 + cc * 2);
                    ldsm_x4(bh4, bh0 + off);
                    ldsm_x4(bl4, bl0 + off);
#pragma unroll
                    for (int mi = 0; mi < 4; mi++) {
                        mma_bf16(acc[mi][2 * njp], afh[mi], bh4);
                        mma_bf16(acc[mi][2 * njp], afh[mi], bl4);
                        mma_bf16(acc[mi][2 * njp], afl[mi], bh4);
                        mma_bf16(acc[mi][2 * njp + 1], afh[mi], bh4 + 2);
                        mma_bf16(acc[mi][2 * njp + 1], afh[mi], bl4 + 2);
                        mma_bf16(acc[mi][2 * njp + 1], afl[mi], bh4 + 2);
                    }
                }
            }
        }
        __syncthreads();
    }
#undef PREFETCH

#pragma unroll
    for (int mi = 0; mi < 4; mi++)
#pragma unroll
        for (int nj = 0; nj < 8; nj++) {
            int r = row0 + wm + mi * 16 + (lane >> 2);
            int c = col0 + wn + nj * 8 + (lane & 3) * 2;
            float* p0 = C + (long long)r * ldc + c;
            p0[0] = acc[mi][nj][0];
            p0[1] = acc[mi][nj][1];
            float* p1 = C + (long long)(r + 8) * ldc + c;
            p1[0] = acc[mi][nj][2];
            p1[1] = acc[mi][nj][3];
        }
}

// Merged Q/K/V projection: grid (48, 16), 128 threads
__global__ __launch_bounds__(128) void tcg_qkv() {
    extern __shared__ char smem[];
    const int cb = blockIdx.x;
    const __nv_bfloat16 *Bh, *Bl; float* C; int ldc, col0;
    if (cb < 32)      { Bh = g_wqh; Bl = g_wql; C = g_q; ldc = DMODEL; col0 = cb * 128; }
    else if (cb < 40) { Bh = g_wkh; Bl = g_wkl; C = g_k; ldc = DKV;    col0 = (cb - 32) * 128; }
    else              { Bh = g_wvh; Bl = g_wvl; C = g_v; ldc = DKV;    col0 = (cb - 40) * 128; }
    gemm_core(g_xh, g_xl, Bh, Bl, C, DMODEL, DMODEL, DMODEL, ldc,
              blockIdx.y * 128, col0, smem);
}

// Generic NT GEMM (wo)
__global__ __launch_bounds__(128) void tcg_nt(
    const __nv_bfloat16* __restrict__ Ah, const __nv_bfloat16* __restrict__ Al,
    const __nv_bfloat16* __restrict__ Bh, const __nv_bfloat16* __restrict__ Bl,
    float* __restrict__ C, int K, int lda, int ldb, int ldc)
{
    extern __shared__ char smem[];
    gemm_core(Ah, Al, Bh, Bl, C, K, lda, ldb, ldc,
              blockIdx.y * 128, blockIdx.x * 128, smem);
}

// ---------------------------------------------------------------------------
// cos/sin tables: bit-identical DP sequence to the original rope arithmetic
// ---------------------------------------------------------------------------
__global__ void init_tables() {
    int s = blockIdx.x;
    int i = threadIdx.x;   // 0..63
    float invf = (float)(1.0 / pow(10000.0, (double)i / 64.0));
    float ang = (float)s * invf;
    double sd, cd;
    sincos((double)ang, &sd, &cd);
    g_cost[s * 64 + i] = (float)cd;
    g_sint[s * 64 + i] = (float)sd;
}

// ---------------------------------------------------------------------------
// RoPE (table-driven): fp32 in, bf16 hi/lo out; Q pre-scaled by 1/sqrt(128)
// ---------------------------------------------------------------------------
__global__ void rope_split() {
    long long idx = (long long)blockIdx.x * blockDim.x + threadIdx.x;
    const long long QP = (long long)S_LEN * HQ * 64;
    const long long KP = (long long)S_LEN * HKV * 64;
    if (idx >= QP + KP) return;

    const float* src; __nv_bfloat16 *dh, *dl;
    int s, h, i, stride; float postscale;
    if (idx < QP) {
        s = (int)(idx / (HQ * 64));
        int rem = (int)(idx % (HQ * 64));
        h = rem / 64; i = rem % 64;
        src = g_q; dh = g_qh; dl = g_ql; stride = DMODEL;
        postscale = 0.08838834764831845f;
    } else {
        long long t = idx - QP;
        s = (int)(t / (HKV * 64));
        int rem = (int)(t % (HKV * 64));
        h = rem / 64; i = rem % 64;
        src = g_k; dh = g_kh; dl = g_kl; stride = DKV;
        postscale = 1.0f;
    }

    float c  = g_cost[s * 64 + i];
    float sn = g_sint[s * 64 + i];

    size_t off = (size_t)s * (size_t)stride + (size_t)h * HD + 2 * (size_t)i;
    float x1 = src[off], x2 = src[off + 1];
    float o1 = (x1 * c - x2 * sn) * postscale;
    float o2 = (x1 * sn + x2 * c) * postscale;
    __nv_bfloat16 h1, h2, l1, l2;
    split2(o1, h1, l1); split2(o2, h2, l2);
    *(uint32_t*)(dh + off) = packpair(h1, h2);
    *(uint32_t*)(dl + off) = packpair(l1, l2);
}

// ---------------------------------------------------------------------------
// Transpose V [s][d] -> Vt [d][s], bf16 hi/lo (proven R13 path)
// ---------------------------------------------------------------------------
__global__ void transpose_v_split() {
    __shared__ float t[32][33];
    int d0 = blockIdx.x * 32;
    int s0 = blockIdx.y * 32;
    for (int i = threadIdx.y; i < 32; i += 8)
        t[i][threadIdx.x] = g_v[(size_t)(s0 + i) * DKV + d0 + threadIdx.x];
    __syncthreads();
    for (int i = threadIdx.y; i < 32; i += 8) {
        float v = t[threadIdx.x][i];
        __nv_bfloat16 h, l;
        split2(v, h, l);
        size_t o = (size_t)(d0 + i) * S_LEN + s0 + threadIdx.x;
        g_vth[o] = h;
        g_vtl[o] = l;
    }
}

// ---------------------------------------------------------------------------
// Flash attention v3 (R13 winner, unchanged)
// ---------------------------------------------------------------------------
#define FB_QH 0
#define FB_QL 34816
#define FB_K(st) (69632 + (st) * 34816)
#define FB_V(st) (139264 + (st) * 36864)
#define FB_SMEM 212992

__global__ __launch_bounds__(256) void flash_attn3() {
    extern __shared__ char smem[];
    const uint32_t sb = smem_u32(smem);

    const int qb   = blockIdx.x;
    const int h    = blockIdx.y;
    const int kvh  = h >> 2;
    const int q0   = qb * 128;
    const int tid  = threadIdx.x;
    const int lane = tid & 31;
    const int w    = tid >> 5;

#pragma unroll
    for (int i = 0; i < 8; i++) {
        int idx = tid + 256 * i;
        int r = idx >> 4;
        int ck = idx & 15;
        uint32_t so = (uint32_t)(r * 272 + ck * 16);
        CP_ASYNC16(sb + FB_QH + so, g_qh + (long long)(q0 + r) * DMODEL + h * HD + ck * 8);
        CP_ASYNC16(sb + FB_QL + so, g_ql + (long long)(q0 + r) * DMODEL + h * HD + ck * 8);
    }
    CP_COMMIT();

#define FB_PREFETCH(kt, st) do {                                              \
    const int s0_ = (kt) * 64;                                                \
    const uint32_t kb_ = sb + FB_K(st);                                       \
    const uint32_t vb_ = sb + FB_V(st);                                       \
    _Pragma("unroll")                                                         \
    for (int i_ = 0; i_ < 4; i_++) {                                          \
        int idx_ = tid + 256 * i_;                                            \
        int r_ = idx_ >> 4;                                                   \
        int ck_ = idx_ & 15;                                                  \
        uint32_t so_ = (uint32_t)(r_ * 272 + ck_ * 16);                       \
        CP_ASYNC16(kb_ + so_,         g_kh + (long long)(s0_ + r_) * DKV + kvh * HD + ck_ * 8); \
        CP_ASYNC16(kb_ + 17408 + so_, g_kl + (long long)(s0_ + r_) * DKV + kvh * HD + ck_ * 8); \
    }                                                                         \
    _Pragma("unroll")                                                         \
    for (int i_ = 0; i_ < 4; i_++) {                                          \
        int idx_ = tid + 256 * i_;                                            \
        int r_ = idx_ >> 3;                                                   \
        int ck_ = idx_ & 7;                                                   \
        uint32_t so_ = (uint32_t)(r_ * 144 + ck_ * 16);                       \
        CP_ASYNC16(vb_ + so_,         g_vth + (long long)(kvh * HD + r_) * S_LEN + s0_ + ck_ * 8); \
        CP_ASYNC16(vb_ + 18432 + so_, g_vtl + (long long)(kvh * HD + r_) * S_LEN + s0_ + ck_ * 8); \
    }                                                                         \
} while (0)

    FB_PREFETCH(0, 0);
    CP_COMMIT();

    CP_WAIT1();
    __syncthreads();

    uint32_t qh_r[8][4], ql_r[8][4];
    {
        int rr = lane & 15;
        int cb2 = (lane >> 4) << 3;
#pragma unroll
        for (int kc = 0; kc < 8; kc++) {
            uint32_t off = (uint32_t)((w * 16 + rr) * 272 + (kc * 16 + cb2) * 2);
            ldsm_x4(qh_r[kc], sb + FB_QH + off);
            ldsm_x4(ql_r[kc], sb + FB_QL + off);
        }
    }

    float out[16][4];
#pragma unroll
    for (int i = 0; i < 16; i++)
#pragma unroll
        for (int e = 0; e < 4; e++) out[i][e] = 0.f;
    float m0 = -1e30f, m1 = -1e30f, l0 = 0.f, l1 = 0.f;

    for (int kt = 0; kt < S_LEN / 64; kt++) {
        __syncthreads();
        if (kt + 1 < S_LEN / 64) {
            FB_PREFETCH(kt + 1, (kt + 1) & 1);
            CP_COMMIT();
            CP_WAIT1();
        } else {
            CP_WAIT0();
        }

        const uint32_t kh0 = sb + FB_K(kt & 1);
        const uint32_t kl0 = kh0 + 17408;
        const uint32_t vh0 = sb + FB_V(kt & 1);
        const uint32_t vl0 = vh0 + 18432;

        float s_acc[8][4];
#pragma unroll
        for (int nj = 0; nj < 8; nj++)
#pragma unroll
            for (int e = 0; e < 4; e++) s_acc[nj][e] = 0.f;

#pragma unroll
        for (int kc = 0; kc < 8; kc++) {
            int rr    = lane & 7;
            int cc    = kc * 16 + (((lane >> 3) & 1) << 3);
            int njoff = (lane >> 4) << 3;
#pragma unroll
            for (int njp = 0; njp < 4; njp++) {
                uint32_t bh4[4], bl4[4];
                uint32_t off = (uint32_t)((njp * 16 + njoff + rr) * 272 + cc * 2);
                ldsm_x4(bh4, kh0 + off);
                ldsm_x4(bl4, kl0 + off);
                mma_bf16(s_acc[2 * njp], qh_r[kc], bh4);
                mma_bf16(s_acc[2 * njp], qh_r[kc], bl4);
                mma_bf16(s_acc[2 * njp], ql_r[kc], bh4);
                mma_bf16(s_acc[2 * njp + 1], qh_r[kc], bh4 + 2);
                mma_bf16(s_acc[2 * njp + 1], qh_r[kc], bl4 + 2);
                mma_bf16(s_acc[2 * njp + 1], ql_r[kc], bh4 + 2);
            }
        }

        float mt0 = -1e30f, mt1 = -1e30f;
#pragma unroll
        for (int nj = 0; nj < 8; nj++) {
            mt0 = fmaxf(mt0, fmaxf(s_acc[nj][0], s_acc[nj][1]));
            mt1 = fmaxf(mt1, fmaxf(s_acc[nj][2], s_acc[nj][3]));
        }
        mt0 = fmaxf(mt0, __shfl_xor_sync(0xffffffffu, mt0, 1));
        mt0 = fmaxf(mt0, __shfl_xor_sync(0xffffffffu, mt0, 2));
        mt1 = fmaxf(mt1, __shfl_xor_sync(0xffffffffu, mt1, 1));
        mt1 = fmaxf(mt1, __shfl_xor_sync(0xffffffffu, mt1, 2));

        float mn0 = fmaxf(m0, mt0), mn1 = fmaxf(m1, mt1);
        float a0 = __expf(m0 - mn0), a1 = __expf(m1 - mn1);
        float sum0 = 0.f, sum1 = 0.f;
#pragma unroll
        for (int nj = 0; nj < 8; nj++) {
            s_acc[nj][0] = __expf(s_acc[nj][0] - mn0);
            s_acc[nj][1] = __expf(s_acc[nj][1] - mn0);
            s_acc[nj][2] = __expf(s_acc[nj][2] - mn1);
            s_acc[nj][3] = __expf(s_acc[nj][3] - mn1);
            sum0 += s_acc[nj][0] + s_acc[nj][1];
            sum1 += s_acc[nj][2] + s_acc[nj][3];
        }
        sum0 += __shfl_xor_sync(0xffffffffu, sum0, 1);
        sum0 += __shfl_xor_sync(0xffffffffu, sum0, 2);
        sum1 += __shfl_xor_sync(0xffffffffu, sum1, 1);
        sum1 += __shfl_xor_sync(0xffffffffu, sum1, 2);
        l0 = l0 * a0 + sum0;  m0 = mn0;
        l1 = l1 * a1 + sum1;  m1 = mn1;
#pragma unroll
        for (int i = 0; i < 16; i++) {
            out[i][0] *= a0; out[i][1] *= a0;
            out[i][2] *= a1; out[i][3] *= a1;
        }

#pragma unroll
        for (int kc = 0; kc < 4; kc++) {
            uint32_t pah[4], pal[4];
            {
                __nv_bfloat16 h0, h1, lo0, lo1;
                split2(s_acc[2 * kc][0], h0, lo0); split2(s_acc[2 * kc][1], h1, lo1);
                pah[0] = packpair(h0, h1); pal[0] = packpair(lo0, lo1);
                split2(s_acc[2 * kc][2], h0, lo0); split2(s_acc[2 * kc][3], h1, lo1);
                pah[1] = packpair(h0, h1); pal[1] = packpair(lo0, lo1);
                split2(s_acc[2 * kc + 1][0], h0, lo0); split2(s_acc[2 * kc + 1][1], h1, lo1);
                pah[2] = packpair(h0, h1); pal[2] = packpair(lo0, lo1);
                split2(s_acc[2 * kc + 1][2], h0, lo0); split2(s_acc[2 * kc + 1][3], h1, lo1);
                pah[3] = packpair(h0, h1); pal[3] = packpair(lo0, lo1);
            }
            int rr    = lane & 7;
            int cc    = kc * 16 + (((lane >> 3) & 1) << 3);
            int ndoff = (lane >> 4) << 3;
#pragma unroll
            for (int ndp = 0; ndp < 8; ndp++) {
                uint32_t vh4[4], vl4[4];
                uint32_t off = (uint32_t)((ndp * 16 + ndoff + rr) * 144 + cc * 2);
                ldsm_x4(vh4, vh0 + off);
                ldsm_x4(vl4, vl0 + off);
                mma_bf16(out[2 * ndp], pah, vh4);
                mma_bf16(out[2 * ndp], pah, vl4);
                mma_bf16(out[2 * ndp], pal, vh4);
                mma_bf16(out[2 * ndp + 1], pah, vh4 + 2);
                mma_bf16(out[2 * ndp + 1], pah, vl4 + 2);
                mma_bf16(out[2 * ndp + 1], pal, vh4 + 2);
            }
        }
    }

    float inv0 = 1.0f / l0, inv1 = 1.0f / l1;
    int row0 = q0 + w * 16 + (lane >> 2);
    int row1 = row0 + 8;
#pragma unroll
    for (int nd = 0; nd < 16; nd++) {
        int col = h * HD + nd * 8 + (lane & 3) * 2;
        __nv_bfloat16 h0, h1, lo0, lo1;
        split2(out[nd][0] * inv0, h0, lo0);
        split2(out[nd][1] * inv0, h1, lo1);
        *(uint32_t*)(g_ah + (size_t)row0 * DMODEL + col) = packpair(h0, h1);
        *(uint32_t*)(g_al + (size_t)row0 * DMODEL + col) = packpair(lo0, lo1);
        split2(out[nd][2] * inv1, h0, lo0);
        split2(out[nd][3] * inv1, h1, lo1);
        *(uint32_t*)(g_ah + (size_t)row1 * DMODEL + col) = packpair(h0, h1);
        *(uint32_t*)(g_al + (size_t)row1 * DMODEL + col) = packpair(lo0, lo1);
    }
}

// ---------------------------------------------------------------------------
// Split: fp32 -> bf16 hi/lo, MLP=4 grid-stride (proven R13 path)
// ---------------------------------------------------------------------------
__global__ void split_f32(const float* __restrict__ in,
                          __nv_bfloat16* __restrict__ hi,
                          __nv_bfloat16* __restrict__ lo, int n4)
{
    const int stride = gridDim.x * blockDim.x;
    const int i0 = blockIdx.x * blockDim.x + threadIdx.x;
    float4 v[4]; int idx[4]; int cnt = 0;
#pragma unroll
    for (int u = 0; u < 4; u++) {
        int j = i0 + u * stride;
        if (j < n4) { idx[cnt] = j; v[cnt] = ((const float4*)in)[j]; cnt++; }
    }
#pragma unroll 4
    for (int t = 0; t < cnt; t++) {
        __nv_bfloat16 h0, h1, h2, h3, l0, l1, l2, l3;
        split2(v[t].x, h0, l0); split2(v[t].y, h1, l1);
        split2(v[t].z, h2, l2); split2(v[t].w, h3, l3);
        ((uint2*)hi)[idx[t]] = make_uint2(packpair(h0, h1), packpair(h2, h3));
        ((uint2*)lo)[idx[t]] = make_uint2(packpair(l0, l1), packpair(l2, l3));
    }
}

// ---------------------------------------------------------------------------
// Launch
// ---------------------------------------------------------------------------
extern "C" void kernel_launch(void* const* d_in, const int* in_sizes, int n_in,
                              void* d_out, int out_size)
{
    const float* x  = (const float*)d_in[0];
    const float* wq = (const float*)d_in[1];
    const float* wk = (const float*)d_in[2];
    const float* wv = (const float*)d_in[3];
    const float* wo = (const float*)d_in[4];
    float* out = (float*)d_out;

    __nv_bfloat16 *xh, *xl, *wqh, *wql, *wkh, *wkl, *wvh, *wvl, *woh, *wol, *ah, *al;
    cudaGetSymbolAddress((void**)&xh,  g_xh);  cudaGetSymbolAddress((void**)&xl,  g_xl);
    cudaGetSymbolAddress((void**)&wqh, g_wqh); cudaGetSymbolAddress((void**)&wql, g_wql);
    cudaGetSymbolAddress((void**)&wkh, g_wkh); cudaGetSymbolAddress((void**)&wkl, g_wkl);
    cudaGetSymbolAddress((void**)&wvh, g_wvh); cudaGetSymbolAddress((void**)&wvl, g_wvl);
    cudaGetSymbolAddress((void**)&woh, g_woh); cudaGetSymbolAddress((void**)&wol, g_wol);
    cudaGetSymbolAddress((void**)&ah,  g_ah);  cudaGetSymbolAddress((void**)&al,  g_al);

    cudaFuncSetAttribute(tcg_nt,
        cudaFuncAttributeMaxDynamicSharedMemorySize, GSMEM);
    cudaFuncSetAttribute(tcg_qkv,
        cudaFuncAttributeMaxDynamicSharedMemorySize, GSMEM);
    cudaFuncSetAttribute(flash_attn3,
        cudaFuncAttributeMaxDynamicSharedMemorySize, FB_SMEM);

#define SPLIT(src, h, l, n) do {                                    \
    int n4 = (int)((n) / 4);                                        \
    int blocks = (n4 + 4 * 256 - 1) / (4 * 256);                    \
    split_f32<<<blocks, 256>>>(src, h, l, n4);                      \
} while (0)

    // 0) tables + split inputs (proven R13 split path)
    init_tables<<<S_LEN, 64>>>();
    SPLIT(x,  xh,  xl,  (long long)S_LEN * DMODEL);
    SPLIT(wq, wqh, wql, (long long)DMODEL * DMODEL);
    SPLIT(wk, wkh, wkl, (long long)DKV * DMODEL);
    SPLIT(wv, wvh, wvl, (long long)DKV * DMODEL);
    SPLIT(wo, woh, wol, (long long)DMODEL * DMODEL);

    // 1) Merged Q/K/V projections
    tcg_qkv<<<dim3(48, 16), 128, GSMEM>>>();

    // 2) RoPE (table-driven) -> bf16 hi/lo Q (pre-scaled), K
    {
        long long total = (long long)S_LEN * HQ * 64 + (long long)S_LEN * HKV * 64;
        rope_split<<<(int)((total + 255) / 256), 256>>>();
    }

    // 3) V transpose -> bf16 hi/lo Vt (proven R13 path)
    transpose_v_split<<<dim3(DKV / 32, S_LEN / 32), dim3(32, 8)>>>();

    // 4) Fused attention v3 -> g_ah/g_al
    flash_attn3<<<dim3(S_LEN / 128, HQ), 256, FB_SMEM>>>();

    // 5) out = attn * wo^T
    tcg_nt<<<dim3(DMODEL / 128, S_LEN / 128), 128, GSMEM>>>(
        ah, al, woh, wol, out, DMODEL, DMODEL, DMODEL, DMODEL);
}